// round 1
// baseline (speedup 1.0000x reference)
#include <cuda_runtime.h>
#include <math.h>

#define BS 8
#define LQ 1000
#define DD 256
#define NH 8
#define NL 4
#define NP 4
#define CC 32
#define LV 8500   // 80*80 + 40*40 + 20*20 + 10*10

// ---------------- scratch (static device globals; no dynamic alloc) --------
__device__ float g_vp  [(size_t)BS * LV * DD];          // projected value  [b, pos, h*32+c]
__device__ float g_off [(size_t)BS * LQ * DD];          // sampling offsets [b, q, 256]
__device__ float g_attn[(size_t)BS * LQ * NH * NL * NP];// attn logits      [b, q, 128]
__device__ float g_tmp [(size_t)BS * LQ * DD];          // aggregated       [b, q, 256]

// ---------------- generic SGEMM: C = A(MxK) @ B(KxN) + bias ----------------
// BM=128, BN=128, BK=8, TM=8, TN=8, 256 threads. N must be a multiple of 128.
__global__ __launch_bounds__(256)
void sgemm_bias(const float* __restrict__ A, const float* __restrict__ B,
                const float* __restrict__ bias, float* __restrict__ Cout,
                int M, int N, int K)
{
    constexpr int BM = 128, BN = 128, BK = 8, TM = 8, TN = 8;
    __shared__ __align__(16) float As[BK][BM];
    __shared__ __align__(16) float Bs[BK][BN];

    const int tid  = threadIdx.x;
    const int brow = blockIdx.y * BM;
    const int bcol = blockIdx.x * BN;

    const int tcol = (tid % (BN / TN)) * TN;   // 16 thread-cols
    const int trow = (tid / (BN / TN)) * TM;   // 16 thread-rows

    float acc[TM][TN];
#pragma unroll
    for (int i = 0; i < TM; i++)
#pragma unroll
        for (int j = 0; j < TN; j++) acc[i][j] = 0.f;

    // loader mapping: 256 threads, one float4 each for A and B tiles
    const int arow  = tid / 2;              // 0..127
    const int acol  = (tid % 2) * 4;        // 0 or 4
    const int browB = tid / 32;             // 0..7
    const int bcolB = (tid % 32) * 4;       // 0..124

    for (int k0 = 0; k0 < K; k0 += BK) {
        float4 av = make_float4(0.f, 0.f, 0.f, 0.f);
        int gr = brow + arow;
        if (gr < M) av = *(const float4*)(A + (size_t)gr * K + k0 + acol);
        As[acol + 0][arow] = av.x;
        As[acol + 1][arow] = av.y;
        As[acol + 2][arow] = av.z;
        As[acol + 3][arow] = av.w;

        float4 bv = *(const float4*)(B + (size_t)(k0 + browB) * N + bcol + bcolB);
        *(float4*)(&Bs[browB][bcolB]) = bv;

        __syncthreads();

#pragma unroll
        for (int kk = 0; kk < BK; kk++) {
            float af[TM], bf[TN];
            float4 a0 = *(const float4*)(&As[kk][trow]);
            float4 a1 = *(const float4*)(&As[kk][trow + 4]);
            af[0]=a0.x; af[1]=a0.y; af[2]=a0.z; af[3]=a0.w;
            af[4]=a1.x; af[5]=a1.y; af[6]=a1.z; af[7]=a1.w;
            float4 b0 = *(const float4*)(&Bs[kk][tcol]);
            float4 b1 = *(const float4*)(&Bs[kk][tcol + 4]);
            bf[0]=b0.x; bf[1]=b0.y; bf[2]=b0.z; bf[3]=b0.w;
            bf[4]=b1.x; bf[5]=b1.y; bf[6]=b1.z; bf[7]=b1.w;
#pragma unroll
            for (int i = 0; i < TM; i++)
#pragma unroll
                for (int j = 0; j < TN; j++)
                    acc[i][j] += af[i] * bf[j];
        }
        __syncthreads();
    }

#pragma unroll
    for (int i = 0; i < TM; i++) {
        int gr = brow + trow + i;
        if (gr >= M) continue;
#pragma unroll
        for (int j = 0; j < TN; j += 4) {
            float4 v;
            v.x = acc[i][j + 0] + bias[bcol + tcol + j + 0];
            v.y = acc[i][j + 1] + bias[bcol + tcol + j + 1];
            v.z = acc[i][j + 2] + bias[bcol + tcol + j + 2];
            v.w = acc[i][j + 3] + bias[bcol + tcol + j + 3];
            *(float4*)(Cout + (size_t)gr * N + bcol + tcol + j) = v;
        }
    }
}

// ---------------- fused softmax + bilinear sampling + aggregation ----------
// One block per (b, q); 8 warps = 8 heads; 32 lanes = 32 channels of the head.
__global__ __launch_bounds__(256)
void sample_agg_kernel(const float* __restrict__ ref)   // [BS, LQ, NL, 2]
{
    const int bq   = blockIdx.x;           // 0 .. BS*LQ-1
    const int b    = bq / LQ;
    const int h    = threadIdx.x >> 5;
    const int lane = threadIdx.x & 31;

    // compile-time level geometry (matches value_spatial_shapes)
    const int   Wl[NL] = {80, 40, 20, 10};
    const int   Hl[NL] = {80, 40, 20, 10};
    const int   St[NL] = {0, 6400, 8000, 8400};

    // ---- softmax over the 16 logits of this head (redundant per lane) ----
    const float* al = g_attn + (size_t)bq * (NH * NL * NP) + h * (NL * NP);
    float logit[NL * NP];
    float m = -1e30f;
#pragma unroll
    for (int i = 0; i < NL * NP; i++) { logit[i] = al[i]; m = fmaxf(m, logit[i]); }
    float s = 0.f;
#pragma unroll
    for (int i = 0; i < NL * NP; i++) { logit[i] = __expf(logit[i] - m); s += logit[i]; }
    const float inv = 1.0f / s;

    const float* ofh = g_off + (size_t)bq * DD + h * (NL * NP * 2);
    const float* vpb = g_vp + (size_t)b * LV * DD + h * CC + lane;

    float acc = 0.f;
#pragma unroll
    for (int l = 0; l < NL; l++) {
        const float rx = ref[((size_t)bq * NL + l) * 2 + 0];
        const float ry = ref[((size_t)bq * NL + l) * 2 + 1];
        const int   W  = Wl[l], H = Hl[l];
        const float Wf = (float)W, Hf = (float)H;
        const size_t base = (size_t)St[l] * DD;
#pragma unroll
        for (int p = 0; p < NP; p++) {
            const float ox = ofh[(l * NP + p) * 2 + 0];
            const float oy = ofh[(l * NP + p) * 2 + 1];
            // x = (rx + ox/W)*W - 0.5 = rx*W + ox - 0.5
            const float x = fmaf(rx, Wf, ox) - 0.5f;
            const float y = fmaf(ry, Hf, oy) - 0.5f;
            const float x0f = floorf(x), y0f = floorf(y);
            const int   x0 = (int)x0f,  y0 = (int)y0f;
            const float fx = x - x0f,   fy = y - y0f;
            const float aw = logit[l * NP + p] * inv;

            const float w00 = (1.f - fx) * (1.f - fy) * aw;
            const float w10 = fx * (1.f - fy) * aw;
            const float w01 = (1.f - fx) * fy * aw;
            const float w11 = fx * fy * aw;

            const bool vx0 = (x0 >= 0) && (x0 < W);
            const bool vx1 = (x0 + 1 >= 0) && (x0 + 1 < W);
            const bool vy0 = (y0 >= 0) && (y0 < H);
            const bool vy1 = (y0 + 1 >= 0) && (y0 + 1 < H);

            if (vy0) {
                const size_t rowb = base + (size_t)y0 * W * DD;
                if (vx0) acc += w00 * vpb[rowb + (size_t)x0 * DD];
                if (vx1) acc += w10 * vpb[rowb + (size_t)(x0 + 1) * DD];
            }
            if (vy1) {
                const size_t rowb = base + (size_t)(y0 + 1) * W * DD;
                if (vx0) acc += w01 * vpb[rowb + (size_t)x0 * DD];
                if (vx1) acc += w11 * vpb[rowb + (size_t)(x0 + 1) * DD];
            }
        }
    }
    g_tmp[(size_t)bq * DD + h * CC + lane] = acc;
}

// ---------------------------------------------------------------------------
extern "C" void kernel_launch(void* const* d_in, const int* in_sizes, int n_in,
                              void* d_out, int out_size)
{
    const float* query  = (const float*)d_in[0];
    const float* refpts = (const float*)d_in[1];
    const float* value  = (const float*)d_in[2];
    const float* w_off  = (const float*)d_in[3];
    const float* b_off  = (const float*)d_in[4];
    const float* w_attn = (const float*)d_in[5];
    const float* b_attn = (const float*)d_in[6];
    const float* w_v    = (const float*)d_in[7];
    const float* b_v    = (const float*)d_in[8];
    const float* w_o    = (const float*)d_in[9];
    const float* b_o    = (const float*)d_in[10];
    float* out = (float*)d_out;

    float *vp, *offp, *attnp, *tmpp;
    cudaGetSymbolAddress((void**)&vp,   g_vp);
    cudaGetSymbolAddress((void**)&offp, g_off);
    cudaGetSymbolAddress((void**)&attnp,g_attn);
    cudaGetSymbolAddress((void**)&tmpp, g_tmp);

    const int Mq = BS * LQ;      // 8000
    const int Mv = BS * LV;      // 68000

    // K1: Vp = value @ w_v + b_v    (68000 x 256 x 256)
    {
        dim3 grid((DD + 127) / 128, (Mv + 127) / 128);
        sgemm_bias<<<grid, 256>>>(value, w_v, b_v, vp, Mv, DD, DD);
    }
    // K2a: off = query @ w_off + b_off   (8000 x 256 x 256)
    {
        dim3 grid((DD + 127) / 128, (Mq + 127) / 128);
        sgemm_bias<<<grid, 256>>>(query, w_off, b_off, offp, Mq, DD, DD);
    }
    // K2b: attn logits = query @ w_attn + b_attn  (8000 x 128 x 256)
    {
        dim3 grid(1, (Mq + 127) / 128);
        sgemm_bias<<<grid, 256>>>(query, w_attn, b_attn, attnp, Mq, NH * NL * NP, DD);
    }
    // K3: softmax + bilinear sampling + aggregation
    sample_agg_kernel<<<Mq, 256>>>(refpts);

    // K4: out = tmp @ w_o + b_o  (8000 x 256 x 256)
    {
        dim3 grid((DD + 127) / 128, (Mq + 127) / 128);
        sgemm_bias<<<grid, 256>>>(tmpp, w_o, b_o, out, Mq, DD, DD);
    }
}

// round 3
// speedup vs baseline: 1.5865x; 1.5865x over previous
#include <cuda_runtime.h>
#include <cstdint>
#include <math.h>

#define BS 8
#define LQ 1000
#define DD 256
#define NH 8
#define NL 4
#define NP 4
#define CC 32
#define LV 8500   // 80*80 + 40*40 + 20*20 + 10*10

// ---------------- scratch (static device globals; no dynamic alloc) --------
__device__ float g_vp  [(size_t)BS * LV * DD];          // projected value  [b, pos, h*32+c]
__device__ float g_off [(size_t)BS * LQ * DD];          // sampling offsets [b, q, 256]
__device__ float g_attn[(size_t)BS * LQ * NH * NL * NP];// attn logits      [b, q, 128]
__device__ float g_tmp [(size_t)BS * LQ * DD];          // aggregated       [b, q, 256]

// =================== tf32 tensor-core GEMM: C = A(MxK)@B(KxN)+bias =========
// Fixed N=256, K=256. BM=128, BN=128, BK=16. 256 threads = 8 warps (4x2).
// Warp tile 32(M) x 64(N) via m16n8k8 tf32 mma.
__device__ __forceinline__ uint32_t f2tf32(float v) {
    uint32_t u;
    asm("cvt.rna.tf32.f32 %0, %1;" : "=r"(u) : "f"(v));
    return u;
}

__global__ __launch_bounds__(256)
void gemm_tf32(const float* __restrict__ A, const float* __restrict__ B,
               const float* __restrict__ bias, float* __restrict__ C, int M)
{
    constexpr int N = 256, K = 256, BM = 128, BN = 128, BK = 16, LDS_ = 136;
    __shared__ uint32_t As[BK][LDS_];   // [k][m], tf32 bits
    __shared__ uint32_t Bs[BK][LDS_];   // [k][n], tf32 bits

    const int tid   = threadIdx.x;
    const int wid   = tid >> 5;
    const int lane  = tid & 31;
    const int wm    = (wid & 3) * 32;       // warp M offset in tile
    const int wn    = (wid >> 2) * 64;      // warp N offset in tile
    const int grp   = lane >> 2;            // 0..7
    const int tig   = lane & 3;             // 0..3

    const int brow = blockIdx.y * BM;
    const int bcol = blockIdx.x * BN;

    float acc[2][8][4];
#pragma unroll
    for (int i = 0; i < 2; i++)
#pragma unroll
        for (int j = 0; j < 8; j++)
#pragma unroll
            for (int r = 0; r < 4; r++) acc[i][j][r] = 0.f;

    // loader mapping
    const int amr = tid >> 2;          // 0..63  (A row within half-tile)
    const int akc = (tid & 3) * 4;     // k offset 0,4,8,12

    for (int k0 = 0; k0 < K; k0 += BK) {
        // ---- load A tile (128 x 16), store transposed [k][m] as tf32 ----
#pragma unroll
        for (int half = 0; half < 2; half++) {
            const int m = amr + half * 64;
            const int gr = brow + m;
            float4 av = make_float4(0.f, 0.f, 0.f, 0.f);
            if (gr < M) av = *(const float4*)(A + (size_t)gr * K + k0 + akc);
            As[akc + 0][m] = f2tf32(av.x);
            As[akc + 1][m] = f2tf32(av.y);
            As[akc + 2][m] = f2tf32(av.z);
            As[akc + 3][m] = f2tf32(av.w);
        }
        // ---- load B tile (16 x 128), [k][n] as tf32 ----
#pragma unroll
        for (int half = 0; half < 2; half++) {
            const int idx = tid + half * 256;      // 0..511
            const int kk  = idx >> 5;              // 0..15
            const int c4  = (idx & 31) * 4;        // 0..124
            float4 bv = *(const float4*)(B + (size_t)(k0 + kk) * N + bcol + c4);
            uint4 tv;
            tv.x = f2tf32(bv.x); tv.y = f2tf32(bv.y);
            tv.z = f2tf32(bv.z); tv.w = f2tf32(bv.w);
            *(uint4*)(&Bs[kk][c4]) = tv;
        }
        __syncthreads();

#pragma unroll
        for (int ks = 0; ks < 2; ks++) {
            const int kb = ks * 8;
            // A fragments for 2 m-tiles
            uint32_t af[2][4];
#pragma unroll
            for (int mi = 0; mi < 2; mi++) {
                const int mb = wm + mi * 16;
                af[mi][0] = As[kb + tig    ][mb + grp    ];
                af[mi][1] = As[kb + tig    ][mb + grp + 8];
                af[mi][2] = As[kb + tig + 4][mb + grp    ];
                af[mi][3] = As[kb + tig + 4][mb + grp + 8];
            }
#pragma unroll
            for (int j = 0; j < 8; j++) {
                const int nb = wn + j * 8;
                uint32_t b0 = Bs[kb + tig    ][nb + grp];
                uint32_t b1 = Bs[kb + tig + 4][nb + grp];
#pragma unroll
                for (int mi = 0; mi < 2; mi++) {
                    asm volatile(
                        "mma.sync.aligned.m16n8k8.row.col.f32.tf32.tf32.f32 "
                        "{%0,%1,%2,%3}, {%4,%5,%6,%7}, {%8,%9}, {%0,%1,%2,%3};"
                        : "+f"(acc[mi][j][0]), "+f"(acc[mi][j][1]),
                          "+f"(acc[mi][j][2]), "+f"(acc[mi][j][3])
                        : "r"(af[mi][0]), "r"(af[mi][1]),
                          "r"(af[mi][2]), "r"(af[mi][3]),
                          "r"(b0), "r"(b1));
                }
            }
        }
        __syncthreads();
    }

    // ---- epilogue: bias + store ----
#pragma unroll
    for (int mi = 0; mi < 2; mi++) {
#pragma unroll
        for (int j = 0; j < 8; j++) {
            const int col = bcol + wn + j * 8 + 2 * tig;
            const float bx = bias[col], by = bias[col + 1];
            int r0 = brow + wm + mi * 16 + grp;
            int r1 = r0 + 8;
            if (r0 < M) {
                float2 v = make_float2(acc[mi][j][0] + bx, acc[mi][j][1] + by);
                *(float2*)(C + (size_t)r0 * N + col) = v;
            }
            if (r1 < M) {
                float2 v = make_float2(acc[mi][j][2] + bx, acc[mi][j][3] + by);
                *(float2*)(C + (size_t)r1 * N + col) = v;
            }
        }
    }
}

// ---------------- generic fp32 SGEMM: C = A(MxK) @ B(KxN) + bias -----------
__global__ __launch_bounds__(256)
void sgemm_bias(const float* __restrict__ A, const float* __restrict__ B,
                const float* __restrict__ bias, float* __restrict__ Cout,
                int M, int N, int K)
{
    constexpr int BM = 128, BN = 128, BK = 8, TM = 8, TN = 8;
    __shared__ __align__(16) float As[BK][BM];
    __shared__ __align__(16) float Bs[BK][BN];

    const int tid  = threadIdx.x;
    const int brow = blockIdx.y * BM;
    const int bcol = blockIdx.x * BN;

    const int tcol = (tid % (BN / TN)) * TN;
    const int trow = (tid / (BN / TN)) * TM;

    float acc[TM][TN];
#pragma unroll
    for (int i = 0; i < TM; i++)
#pragma unroll
        for (int j = 0; j < TN; j++) acc[i][j] = 0.f;

    const int arow  = tid / 2;
    const int acol  = (tid % 2) * 4;
    const int browB = tid / 32;
    const int bcolB = (tid % 32) * 4;

    for (int k0 = 0; k0 < K; k0 += BK) {
        float4 av = make_float4(0.f, 0.f, 0.f, 0.f);
        int gr = brow + arow;
        if (gr < M) av = *(const float4*)(A + (size_t)gr * K + k0 + acol);
        As[acol + 0][arow] = av.x;
        As[acol + 1][arow] = av.y;
        As[acol + 2][arow] = av.z;
        As[acol + 3][arow] = av.w;

        float4 bv = *(const float4*)(B + (size_t)(k0 + browB) * N + bcol + bcolB);
        *(float4*)(&Bs[browB][bcolB]) = bv;

        __syncthreads();

#pragma unroll
        for (int kk = 0; kk < BK; kk++) {
            float af[TM], bf[TN];
            float4 a0 = *(const float4*)(&As[kk][trow]);
            float4 a1 = *(const float4*)(&As[kk][trow + 4]);
            af[0]=a0.x; af[1]=a0.y; af[2]=a0.z; af[3]=a0.w;
            af[4]=a1.x; af[5]=a1.y; af[6]=a1.z; af[7]=a1.w;
            float4 b0 = *(const float4*)(&Bs[kk][tcol]);
            float4 b1 = *(const float4*)(&Bs[kk][tcol + 4]);
            bf[0]=b0.x; bf[1]=b0.y; bf[2]=b0.z; bf[3]=b0.w;
            bf[4]=b1.x; bf[5]=b1.y; bf[6]=b1.z; bf[7]=b1.w;
#pragma unroll
            for (int i = 0; i < TM; i++)
#pragma unroll
                for (int j = 0; j < TN; j++)
                    acc[i][j] += af[i] * bf[j];
        }
        __syncthreads();
    }

#pragma unroll
    for (int i = 0; i < TM; i++) {
        int gr = brow + trow + i;
        if (gr >= M) continue;
#pragma unroll
        for (int j = 0; j < TN; j += 4) {
            float4 v;
            v.x = acc[i][j + 0] + bias[bcol + tcol + j + 0];
            v.y = acc[i][j + 1] + bias[bcol + tcol + j + 1];
            v.z = acc[i][j + 2] + bias[bcol + tcol + j + 2];
            v.w = acc[i][j + 3] + bias[bcol + tcol + j + 3];
            *(float4*)(Cout + (size_t)gr * N + bcol + tcol + j) = v;
        }
    }
}

// ---------------- fused softmax + bilinear sampling + aggregation ----------
// One block per (b, q). Phase 1: 128 threads each handle one (h,l,p) point:
// 16-wide shuffle softmax + bilinear weights & element-base indices -> smem.
// Phase 2: 8 warps (one per head) x 32 lanes (channels) gather + FMA.
__global__ __launch_bounds__(256)
void sample_agg_kernel(const float* __restrict__ ref)   // [BS, LQ, NL, 2]
{
    __shared__ float sw [128][4];
    __shared__ int   sidx[128][4];

    const int bq  = blockIdx.x;
    const int b   = bq / LQ;
    const int tid = threadIdx.x;

    const int Wl[NL] = {80, 40, 20, 10};
    const int St[NL] = {0, 6400, 8000, 8400};

    if (tid < 128) {
        const int t = tid;          // point id: h*16 + l*4 + p
        const int h = t >> 4;
        const int i = t & 15;
        const int l = i >> 2;

        // softmax over the 16 points of this head (16-wide shuffles)
        float logit = g_attn[(size_t)bq * 128 + t];
        float m = logit;
#pragma unroll
        for (int d = 8; d; d >>= 1) m = fmaxf(m, __shfl_xor_sync(0xffffffffu, m, d, 16));
        float e = __expf(logit - m);
        float s = e;
#pragma unroll
        for (int d = 8; d; d >>= 1) s += __shfl_xor_sync(0xffffffffu, s, d, 16);
        const float aw = e / s;

        const float ox = g_off[(size_t)bq * DD + 2 * t];
        const float oy = g_off[(size_t)bq * DD + 2 * t + 1];
        const float rx = ref[((size_t)bq * NL + l) * 2 + 0];
        const float ry = ref[((size_t)bq * NL + l) * 2 + 1];

        const int   W = Wl[l], H = Wl[l];
        const float Wf = (float)W;

        const float x = fmaf(rx, Wf, ox) - 0.5f;
        const float y = fmaf(ry, Wf, oy) - 0.5f;
        const float x0f = floorf(x), y0f = floorf(y);
        const int   x0 = (int)x0f,  y0 = (int)y0f;
        const float fx = x - x0f,   fy = y - y0f;

        const float w00 = (1.f - fx) * (1.f - fy) * aw;
        const float w10 = fx * (1.f - fy) * aw;
        const float w01 = (1.f - fx) * fy * aw;
        const float w11 = fx * fy * aw;

        const bool vx0 = (x0 >= 0) && (x0 < W);
        const bool vx1 = (x0 + 1 >= 0) && (x0 + 1 < W);
        const bool vy0 = (y0 >= 0) && (y0 < H);
        const bool vy1 = (y0 + 1 >= 0) && (y0 + 1 < H);

        const int pbase = (b * LV + St[l]) ;     // position base
        const int hoff  = h * CC;

        const int i00 = (pbase + y0 * W + x0) * DD + hoff;
        const int i10 = i00 + DD;
        const int i01 = i00 + W * DD;
        const int i11 = i01 + DD;

        sw[t][0] = (vx0 && vy0) ? w00 : 0.f;  sidx[t][0] = (vx0 && vy0) ? i00 : 0;
        sw[t][1] = (vx1 && vy0) ? w10 : 0.f;  sidx[t][1] = (vx1 && vy0) ? i10 : 0;
        sw[t][2] = (vx0 && vy1) ? w01 : 0.f;  sidx[t][2] = (vx0 && vy1) ? i01 : 0;
        sw[t][3] = (vx1 && vy1) ? w11 : 0.f;  sidx[t][3] = (vx1 && vy1) ? i11 : 0;
    }
    __syncthreads();

    const int h    = tid >> 5;
    const int lane = tid & 31;
    float acc = 0.f;
#pragma unroll
    for (int i = 0; i < 16; i++) {
        const int t = h * 16 + i;
#pragma unroll
        for (int c = 0; c < 4; c++) {
            const float w = sw[t][c];
            const int   idx = sidx[t][c];
            acc = fmaf(w, __ldg(&g_vp[(size_t)idx + lane]), acc);
        }
    }
    g_tmp[(size_t)bq * DD + h * CC + lane] = acc;
}

// ---------------------------------------------------------------------------
extern "C" void kernel_launch(void* const* d_in, const int* in_sizes, int n_in,
                              void* d_out, int out_size)
{
    const float* query  = (const float*)d_in[0];
    const float* refpts = (const float*)d_in[1];
    const float* value  = (const float*)d_in[2];
    const float* w_off  = (const float*)d_in[3];
    const float* b_off  = (const float*)d_in[4];
    const float* w_attn = (const float*)d_in[5];
    const float* b_attn = (const float*)d_in[6];
    const float* w_v    = (const float*)d_in[7];
    const float* b_v    = (const float*)d_in[8];
    const float* w_o    = (const float*)d_in[9];
    const float* b_o    = (const float*)d_in[10];
    float* out = (float*)d_out;

    float *vp, *offp, *attnp, *tmpp;
    cudaGetSymbolAddress((void**)&vp,   g_vp);
    cudaGetSymbolAddress((void**)&offp, g_off);
    cudaGetSymbolAddress((void**)&attnp,g_attn);
    cudaGetSymbolAddress((void**)&tmpp, g_tmp);

    const int Mq = BS * LQ;      // 8000
    const int Mv = BS * LV;      // 68000

    // K1: Vp = value @ w_v + b_v    (68000 x 256 x 256)  -- tf32 tensor cores
    {
        dim3 grid(2, (Mv + 127) / 128);
        gemm_tf32<<<grid, 256>>>(value, w_v, b_v, vp, Mv);
    }
    // K2a: off = query @ w_off + b_off   (8000 x 256 x 256)  -- fp32
    {
        dim3 grid(2, (Mq + 127) / 128);
        sgemm_bias<<<grid, 256>>>(query, w_off, b_off, offp, Mq, DD, DD);
    }
    // K2b: attn logits = query @ w_attn + b_attn  (8000 x 128 x 256) -- fp32
    {
        dim3 grid(1, (Mq + 127) / 128);
        sgemm_bias<<<grid, 256>>>(query, w_attn, b_attn, attnp, Mq, NH * NL * NP, DD);
    }
    // K3: softmax + bilinear sampling + aggregation
    sample_agg_kernel<<<Mq, 256>>>(refpts);

    // K4: out = tmp @ w_o + b_o  (8000 x 256 x 256) -- fp32
    {
        dim3 grid(2, (Mq + 127) / 128);
        sgemm_bias<<<grid, 256>>>(tmpp, w_o, b_o, out, Mq, DD, DD);
    }
}

// round 4
// speedup vs baseline: 2.5280x; 1.5934x over previous
#include <cuda_runtime.h>
#include <cstdint>
#include <math.h>

#define BS 8
#define LQ 1000
#define DD 256
#define NH 8
#define NL 4
#define NP 4
#define CC 32
#define LV 8500   // 80*80 + 40*40 + 20*20 + 10*10

// ---------------- scratch (static device globals; no dynamic alloc) --------
__device__ float g_vp  [(size_t)BS * LV * DD];          // projected value  [b, pos, h*32+c]
__device__ float g_off [(size_t)BS * LQ * DD];          // sampling offsets [b, q, 256]
__device__ float g_attn[(size_t)BS * LQ * NH * NL * NP];// attn logits      [b, q, 128]
__device__ float g_tmp [(size_t)BS * LQ * DD];          // aggregated       [b, q, 256]

__device__ __forceinline__ uint32_t f2tf32(float v) {
    uint32_t u;
    asm("cvt.rna.tf32.f32 %0, %1;" : "=r"(u) : "f"(v));
    return u;
}

__device__ __forceinline__ void cpasync16(uint32_t dst, const void* src) {
    asm volatile("cp.async.cg.shared.global [%0], [%1], 16;" :: "r"(dst), "l"(src));
}
__device__ __forceinline__ void cp_commit() {
    asm volatile("cp.async.commit_group;");
}
__device__ __forceinline__ void cp_wait0() {
    asm volatile("cp.async.wait_group 0;");
}

// =================== tf32 tensor-core GEMM: C = A(MxK)@B(KxN)+bias =========
// K=256 fixed. BM=128, BN=128 (tile), BK=16, 2-stage cp.async pipeline.
// 256 threads = 8 warps (4 in M x 2 in N); warp tile 32(M) x 64(N).
// N = runtime column count / row stride (multiple of 128).
__global__ __launch_bounds__(256)
void gemm_tf32(const float* __restrict__ A, const float* __restrict__ B,
               const float* __restrict__ bias, float* __restrict__ C,
               int M, int N)
{
    constexpr int K = 256, BK = 16, NIT = K / BK;
    constexpr int LDA = 20;    // A smem row stride (floats): 16 data + 4 pad
    constexpr int LDB = 136;   // B smem row stride (floats)

    __shared__ float As[2][128][LDA];   // [buf][m][k]  fp32
    __shared__ float Bs[2][BK][LDB];    // [buf][k][n]  fp32

    const int tid  = threadIdx.x;
    const int wid  = tid >> 5;
    const int lane = tid & 31;
    const int wm   = (wid & 3) * 32;
    const int wn   = (wid >> 2) * 64;
    const int grp  = lane >> 2;     // 0..7
    const int tig  = lane & 3;      // 0..3

    const int brow = blockIdx.y * 128;
    const int bcol = blockIdx.x * 128;

    float acc[2][8][4];
#pragma unroll
    for (int i = 0; i < 2; i++)
#pragma unroll
        for (int j = 0; j < 8; j++)
#pragma unroll
            for (int r = 0; r < 4; r++) acc[i][j][r] = 0.f;

    // loader mapping
    const int arow = tid >> 1;                 // 0..127
    const int ak0  = (tid & 1) * 8;            // k offset 0 or 8 (two 16B chunks)
    const int agr  = min(brow + arow, M - 1);  // clamped source row

    const uint32_t sbaseA = (uint32_t)__cvta_generic_to_shared(&As[0][0][0]);
    const uint32_t sbaseB = (uint32_t)__cvta_generic_to_shared(&Bs[0][0][0]);

    auto load_tiles = [&](int k0, int buf) {
        // A tile: 128 x 16 fp32; each thread two 16B chunks
        const float* srcA = A + (size_t)agr * K + k0 + ak0;
        uint32_t dstA = sbaseA + (uint32_t)(buf * 128 * LDA + arow * LDA + ak0) * 4u;
        cpasync16(dstA,      srcA);
        cpasync16(dstA + 16, srcA + 4);
        // B tile: 16 x 128 fp32; each thread two 16B chunks
#pragma unroll
        for (int half = 0; half < 2; half++) {
            const int idx = tid + half * 256;     // 0..511
            const int kk  = idx >> 5;             // 0..15
            const int c   = (idx & 31) * 4;       // 0..124
            const float* srcB = B + (size_t)(k0 + kk) * N + bcol + c;
            uint32_t dstB = sbaseB + (uint32_t)(buf * BK * LDB + kk * LDB + c) * 4u;
            cpasync16(dstB, srcB);
        }
        cp_commit();
    };

    load_tiles(0, 0);

    for (int it = 0; it < NIT; it++) {
        const int cur = it & 1;
        cp_wait0();
        __syncthreads();
        if (it + 1 < NIT) load_tiles((it + 1) * BK, cur ^ 1);

#pragma unroll
        for (int ks = 0; ks < 2; ks++) {
            const int kb = ks * 8;
            uint32_t af[2][4];
#pragma unroll
            for (int mi = 0; mi < 2; mi++) {
                const int mb = wm + mi * 16;
                af[mi][0] = f2tf32(As[cur][mb + grp    ][kb + tig    ]);
                af[mi][1] = f2tf32(As[cur][mb + grp + 8][kb + tig    ]);
                af[mi][2] = f2tf32(As[cur][mb + grp    ][kb + tig + 4]);
                af[mi][3] = f2tf32(As[cur][mb + grp + 8][kb + tig + 4]);
            }
#pragma unroll
            for (int j = 0; j < 8; j++) {
                const int nb = wn + j * 8;
                uint32_t b0 = f2tf32(Bs[cur][kb + tig    ][nb + grp]);
                uint32_t b1 = f2tf32(Bs[cur][kb + tig + 4][nb + grp]);
#pragma unroll
                for (int mi = 0; mi < 2; mi++) {
                    asm volatile(
                        "mma.sync.aligned.m16n8k8.row.col.f32.tf32.tf32.f32 "
                        "{%0,%1,%2,%3}, {%4,%5,%6,%7}, {%8,%9}, {%0,%1,%2,%3};"
                        : "+f"(acc[mi][j][0]), "+f"(acc[mi][j][1]),
                          "+f"(acc[mi][j][2]), "+f"(acc[mi][j][3])
                        : "r"(af[mi][0]), "r"(af[mi][1]),
                          "r"(af[mi][2]), "r"(af[mi][3]),
                          "r"(b0), "r"(b1));
                }
            }
        }
        __syncthreads();
    }

    // ---- epilogue: bias + store ----
#pragma unroll
    for (int mi = 0; mi < 2; mi++) {
#pragma unroll
        for (int j = 0; j < 8; j++) {
            const int col = bcol + wn + j * 8 + 2 * tig;
            const float bx = bias[col], by = bias[col + 1];
            int r0 = brow + wm + mi * 16 + grp;
            int r1 = r0 + 8;
            if (r0 < M) {
                float2 v = make_float2(acc[mi][j][0] + bx, acc[mi][j][1] + by);
                *(float2*)(C + (size_t)r0 * N + col) = v;
            }
            if (r1 < M) {
                float2 v = make_float2(acc[mi][j][2] + bx, acc[mi][j][3] + by);
                *(float2*)(C + (size_t)r1 * N + col) = v;
            }
        }
    }
}

// ---------------- fused softmax + bilinear sampling + aggregation ----------
// One block per (b, q). Phase 1: 128 threads each handle one (h,l,p) point:
// 16-wide shuffle softmax + bilinear weights & byte offsets -> smem (packed).
// Phase 2: 8 warps (one per head) x 32 lanes (channels) gather + FMA.
__global__ __launch_bounds__(256)
void sample_agg_kernel(const float* __restrict__ ref)   // [BS, LQ, NL, 2]
{
    __shared__ __align__(16) float2 swo[128][4];   // .x = weight, .y = byte offset (as int bits)

    const int bq  = blockIdx.x;
    const int b   = bq / LQ;
    const int tid = threadIdx.x;

    const int Wl[NL] = {80, 40, 20, 10};
    const int St[NL] = {0, 6400, 8000, 8400};

    if (tid < 128) {
        const int t = tid;          // point id: h*16 + l*4 + p
        const int h = t >> 4;
        const int i = t & 15;
        const int l = i >> 2;

        float logit = g_attn[(size_t)bq * 128 + t];
        float m = logit;
#pragma unroll
        for (int d = 8; d; d >>= 1) m = fmaxf(m, __shfl_xor_sync(0xffffffffu, m, d, 16));
        float e = __expf(logit - m);
        float s = e;
#pragma unroll
        for (int d = 8; d; d >>= 1) s += __shfl_xor_sync(0xffffffffu, s, d, 16);
        const float aw = e / s;

        const float ox = g_off[(size_t)bq * DD + 2 * t];
        const float oy = g_off[(size_t)bq * DD + 2 * t + 1];
        const float rx = ref[((size_t)bq * NL + l) * 2 + 0];
        const float ry = ref[((size_t)bq * NL + l) * 2 + 1];

        const int   W = Wl[l], H = Wl[l];
        const float Wf = (float)W;

        const float x = fmaf(rx, Wf, ox) - 0.5f;
        const float y = fmaf(ry, Wf, oy) - 0.5f;
        const float x0f = floorf(x), y0f = floorf(y);
        const int   x0 = (int)x0f,  y0 = (int)y0f;
        const float fx = x - x0f,   fy = y - y0f;

        const float w00 = (1.f - fx) * (1.f - fy) * aw;
        const float w10 = fx * (1.f - fy) * aw;
        const float w01 = (1.f - fx) * fy * aw;
        const float w11 = fx * fy * aw;

        const bool vx0 = (x0 >= 0) && (x0 < W);
        const bool vx1 = (x0 + 1 >= 0) && (x0 + 1 < W);
        const bool vy0 = (y0 >= 0) && (y0 < H);
        const bool vy1 = (y0 + 1 >= 0) && (y0 + 1 < H);

        const int pbase = b * LV + St[l];
        const int hoff  = h * CC;

        const int i00 = ((pbase + y0 * W + x0) * DD + hoff) << 2;   // byte offsets
        const int i10 = i00 + (DD << 2);
        const int i01 = i00 + (W * DD << 2);
        const int i11 = i01 + (DD << 2);

        swo[t][0] = make_float2((vx0 && vy0) ? w00 : 0.f, __int_as_float((vx0 && vy0) ? i00 : 0));
        swo[t][1] = make_float2((vx1 && vy0) ? w10 : 0.f, __int_as_float((vx1 && vy0) ? i10 : 0));
        swo[t][2] = make_float2((vx0 && vy1) ? w01 : 0.f, __int_as_float((vx0 && vy1) ? i01 : 0));
        swo[t][3] = make_float2((vx1 && vy1) ? w11 : 0.f, __int_as_float((vx1 && vy1) ? i11 : 0));
    }
    __syncthreads();

    const int h    = tid >> 5;
    const int lane = tid & 31;
    const char* base = (const char*)g_vp + (lane << 2);
    float acc = 0.f;
#pragma unroll
    for (int i = 0; i < 16; i++) {
        const int t = h * 16 + i;
        float4 p01 = *(const float4*)(&swo[t][0]);
        float4 p23 = *(const float4*)(&swo[t][2]);
        acc = fmaf(p01.x, *(const float*)(base + __float_as_int(p01.y)), acc);
        acc = fmaf(p01.z, *(const float*)(base + __float_as_int(p01.w)), acc);
        acc = fmaf(p23.x, *(const float*)(base + __float_as_int(p23.y)), acc);
        acc = fmaf(p23.z, *(const float*)(base + __float_as_int(p23.w)), acc);
    }
    g_tmp[(size_t)bq * DD + h * CC + lane] = acc;
}

// ---------------------------------------------------------------------------
extern "C" void kernel_launch(void* const* d_in, const int* in_sizes, int n_in,
                              void* d_out, int out_size)
{
    const float* query  = (const float*)d_in[0];
    const float* refpts = (const float*)d_in[1];
    const float* value  = (const float*)d_in[2];
    const float* w_off  = (const float*)d_in[3];
    const float* b_off  = (const float*)d_in[4];
    const float* w_attn = (const float*)d_in[5];
    const float* b_attn = (const float*)d_in[6];
    const float* w_v    = (const float*)d_in[7];
    const float* b_v    = (const float*)d_in[8];
    const float* w_o    = (const float*)d_in[9];
    const float* b_o    = (const float*)d_in[10];
    float* out = (float*)d_out;

    float *vp, *offp, *attnp, *tmpp;
    cudaGetSymbolAddress((void**)&vp,   g_vp);
    cudaGetSymbolAddress((void**)&offp, g_off);
    cudaGetSymbolAddress((void**)&attnp,g_attn);
    cudaGetSymbolAddress((void**)&tmpp, g_tmp);

    const int Mq = BS * LQ;      // 8000
    const int Mv = BS * LV;      // 68000

    // K1: Vp = value @ w_v + b_v    (68000 x 256 x 256)
    {
        dim3 grid(2, (Mv + 127) / 128);
        gemm_tf32<<<grid, 256>>>(value, w_v, b_v, vp, Mv, DD);
    }
    // K2a: off = query @ w_off + b_off   (8000 x 256 x 256)
    {
        dim3 grid(2, (Mq + 127) / 128);
        gemm_tf32<<<grid, 256>>>(query, w_off, b_off, offp, Mq, DD);
    }
    // K2b: attn logits = query @ w_attn + b_attn  (8000 x 128 x 256)
    {
        dim3 grid(1, (Mq + 127) / 128);
        gemm_tf32<<<grid, 256>>>(query, w_attn, b_attn, attnp, Mq, NH * NL * NP);
    }
    // K3: softmax + bilinear sampling + aggregation
    sample_agg_kernel<<<Mq, 256>>>(refpts);

    // K4: out = tmp @ w_o + b_o  (8000 x 256 x 256)
    {
        dim3 grid(2, (Mq + 127) / 128);
        gemm_tf32<<<grid, 256>>>(tmpp, w_o, b_o, out, Mq, DD);
    }
}

// round 8
// speedup vs baseline: 3.3435x; 1.3226x over previous
#include <cuda_runtime.h>
#include <cuda_fp16.h>
#include <cstdint>
#include <math.h>

#define BS 8
#define LQ 1000
#define DD 256
#define NH 8
#define NL 4
#define NP 4
#define CC 32
#define LV 8500   // 80*80 + 40*40 + 20*20 + 10*10

// ---------------- scratch (static device globals; no dynamic alloc) --------
__device__ __align__(16) __half g_vh  [(size_t)BS * LV * DD];   // value fp16
__device__ __align__(16) __half g_qh  [(size_t)BS * LQ * DD];   // query fp16
__device__ __align__(16) __half g_vph [(size_t)BS * LV * DD];   // projected value fp16
__device__ __align__(16) float  g_off [(size_t)BS * LQ * DD];
__device__ __align__(16) float  g_attn[(size_t)BS * LQ * NH * NL * NP];
__device__ __align__(16) __half g_tmph[(size_t)BS * LQ * DD];   // aggregated fp16
__device__ __align__(16) __half g_wvT  [DD * DD];               // [N][K] fp16
__device__ __align__(16) __half g_woffT[DD * DD];
__device__ __align__(16) __half g_wattnT[(NH*NL*NP) * DD];
__device__ __align__(16) __half g_woT  [DD * DD];

// ======================= helpers ===========================================
__device__ __forceinline__ void cpasync16(uint32_t dst, const void* src) {
    asm volatile("cp.async.cg.shared.global [%0], [%1], 16;" :: "r"(dst), "l"(src));
}
__device__ __forceinline__ void cp_commit() { asm volatile("cp.async.commit_group;"); }

// ============== fp16 tensor-core GEMM: C = A(Mx256) @ BT^T + bias ==========
// A: [M][256] fp16, BT: [N][256] fp16 (K-major). Block tile 128x128, BK=32.
// 256 threads = 8 warps (4 M x 2 N), warp tile 32x64, m16n8k16.
#define LDH 40   // smem row stride in halves (64B data + 16B pad)

__global__ __launch_bounds__(256)
void gemm_h16(const __half* __restrict__ A, const __half* __restrict__ BT,
              const float* __restrict__ bias, float* __restrict__ Cf,
              __half* __restrict__ Ch, int M, int N)
{
    __shared__ __align__(16) __half As[2][128][LDH];
    __shared__ __align__(16) __half Bs[2][128][LDH];

    const int tid  = threadIdx.x;
    const int wid  = tid >> 5;
    const int lane = tid & 31;
    const int wm   = (wid & 3) * 32;
    const int wn   = (wid >> 2) * 64;
    const int grp  = lane >> 2;
    const int tig  = lane & 3;

    const int brow = blockIdx.x * 128;
    const int ncol = blockIdx.y * 128;

    float acc[2][8][4];
#pragma unroll
    for (int i = 0; i < 2; i++)
#pragma unroll
        for (int j = 0; j < 8; j++)
#pragma unroll
            for (int r = 0; r < 4; r++) acc[i][j][r] = 0.f;

    auto load = [&](int kb, int buf) {
#pragma unroll
        for (int t = 0; t < 2; t++) {
            const int lin = tid + t * 256;     // 0..511
            const int row = lin >> 2;          // 0..127
            const int c   = lin & 3;           // 16B chunk
            const __half* sa = A + (size_t)min(brow + row, M - 1) * 256 + kb + c * 8;
            cpasync16((uint32_t)__cvta_generic_to_shared(&As[buf][row][c * 8]), sa);
            const __half* sb = BT + (size_t)(ncol + row) * 256 + kb + c * 8;
            cpasync16((uint32_t)__cvta_generic_to_shared(&Bs[buf][row][c * 8]), sb);
        }
        cp_commit();
    };

    load(0, 0);

    for (int it = 0; it < 8; it++) {
        const int buf = it & 1;
        if (it + 1 < 8) {
            load((it + 1) * 32, buf ^ 1);
            asm volatile("cp.async.wait_group 1;");
        } else {
            asm volatile("cp.async.wait_group 0;");
        }
        __syncthreads();

#pragma unroll
        for (int ks = 0; ks < 2; ks++) {
            const int kh = ks * 16;
            uint32_t af[2][4];
#pragma unroll
            for (int mi = 0; mi < 2; mi++) {
                const int r0 = wm + mi * 16 + grp;
                af[mi][0] = *(const uint32_t*)&As[buf][r0    ][kh + tig * 2];
                af[mi][1] = *(const uint32_t*)&As[buf][r0 + 8][kh + tig * 2];
                af[mi][2] = *(const uint32_t*)&As[buf][r0    ][kh + tig * 2 + 8];
                af[mi][3] = *(const uint32_t*)&As[buf][r0 + 8][kh + tig * 2 + 8];
            }
#pragma unroll
            for (int j = 0; j < 8; j++) {
                const int nr = wn + j * 8 + grp;
                uint32_t b0 = *(const uint32_t*)&Bs[buf][nr][kh + tig * 2];
                uint32_t b1 = *(const uint32_t*)&Bs[buf][nr][kh + tig * 2 + 8];
#pragma unroll
                for (int mi = 0; mi < 2; mi++) {
                    asm volatile(
                        "mma.sync.aligned.m16n8k16.row.col.f32.f16.f16.f32 "
                        "{%0,%1,%2,%3}, {%4,%5,%6,%7}, {%8,%9}, {%0,%1,%2,%3};"
                        : "+f"(acc[mi][j][0]), "+f"(acc[mi][j][1]),
                          "+f"(acc[mi][j][2]), "+f"(acc[mi][j][3])
                        : "r"(af[mi][0]), "r"(af[mi][1]),
                          "r"(af[mi][2]), "r"(af[mi][3]),
                          "r"(b0), "r"(b1));
                }
            }
        }
        __syncthreads();
    }

    // ---- epilogue ----
#pragma unroll
    for (int mi = 0; mi < 2; mi++) {
#pragma unroll
        for (int j = 0; j < 8; j++) {
            const int col = ncol + wn + j * 8 + 2 * tig;
            const float bx = bias[col], by = bias[col + 1];
            const int r0 = brow + wm + mi * 16 + grp;
            const int r1 = r0 + 8;
            if (Ch) {
                if (r0 < M)
                    *(__half2*)(Ch + (size_t)r0 * N + col) =
                        __floats2half2_rn(acc[mi][j][0] + bx, acc[mi][j][1] + by);
                if (r1 < M)
                    *(__half2*)(Ch + (size_t)r1 * N + col) =
                        __floats2half2_rn(acc[mi][j][2] + bx, acc[mi][j][3] + by);
            } else {
                if (r0 < M)
                    *(float2*)(Cf + (size_t)r0 * N + col) =
                        make_float2(acc[mi][j][0] + bx, acc[mi][j][1] + by);
                if (r1 < M)
                    *(float2*)(Cf + (size_t)r1 * N + col) =
                        make_float2(acc[mi][j][2] + bx, acc[mi][j][3] + by);
            }
        }
    }
}

// ==================== fp32 -> fp16 elementwise (n % 4 == 0) ================
__global__ __launch_bounds__(256)
void f32_to_f16(const float* __restrict__ src, __half* __restrict__ dst, int n)
{
    const int i = (blockIdx.x * 256 + threadIdx.x) * 4;
    if (i < n) {
        float4 v = *(const float4*)(src + i);
        __half2 h0 = __floats2half2_rn(v.x, v.y);
        __half2 h1 = __floats2half2_rn(v.z, v.w);
        *(__half2*)(dst + i)     = h0;
        *(__half2*)(dst + i + 2) = h1;
    }
}

// ============ transpose+convert: dst_h[N][256] = f16(src[256][N]) ==========
__global__ void transpose_w_h(const float* __restrict__ src, __half* __restrict__ dst, int N)
{
    __shared__ float t[32][33];
    const int n0 = blockIdx.x * 32;
    const int k0 = blockIdx.y * 32;
    const int x = threadIdx.x, y = threadIdx.y;   // 32 x 8
#pragma unroll
    for (int i = 0; i < 32; i += 8)
        t[y + i][x] = src[(size_t)(k0 + y + i) * N + n0 + x];
    __syncthreads();
#pragma unroll
    for (int i = 0; i < 32; i += 8)
        dst[(size_t)(n0 + y + i) * 256 + k0 + x] = __float2half(t[x][y + i]);
}

// ---------------- fused softmax + bilinear sampling + aggregation ----------
__global__ __launch_bounds__(256)
void sample_agg_kernel(const float* __restrict__ ref)
{
    __shared__ __align__(16) float2 swo[128][4];   // .x weight, .y byte offset

    const int bq  = blockIdx.x;
    const int b   = bq / LQ;
    const int tid = threadIdx.x;

    const int Wl[NL] = {80, 40, 20, 10};
    const int St[NL] = {0, 6400, 8000, 8400};

    if (tid < 128) {
        const int t = tid;
        const int h = t >> 4;
        const int i = t & 15;
        const int l = i >> 2;

        float logit = g_attn[(size_t)bq * 128 + t];
        float m = logit;
#pragma unroll
        for (int d = 8; d; d >>= 1) m = fmaxf(m, __shfl_xor_sync(0xffffffffu, m, d, 16));
        float e = __expf(logit - m);
        float s = e;
#pragma unroll
        for (int d = 8; d; d >>= 1) s += __shfl_xor_sync(0xffffffffu, s, d, 16);
        const float aw = e / s;

        const float ox = g_off[(size_t)bq * DD + 2 * t];
        const float oy = g_off[(size_t)bq * DD + 2 * t + 1];
        const float rx = ref[((size_t)bq * NL + l) * 2 + 0];
        const float ry = ref[((size_t)bq * NL + l) * 2 + 1];

        const int   W = Wl[l], H = Wl[l];
        const float Wf = (float)W;

        const float x = fmaf(rx, Wf, ox) - 0.5f;
        const float y = fmaf(ry, Wf, oy) - 0.5f;
        const float x0f = floorf(x), y0f = floorf(y);
        const int   x0 = (int)x0f,  y0 = (int)y0f;
        const float fx = x - x0f,   fy = y - y0f;

        const float w00 = (1.f - fx) * (1.f - fy) * aw;
        const float w10 = fx * (1.f - fy) * aw;
        const float w01 = (1.f - fx) * fy * aw;
        const float w11 = fx * fy * aw;

        const bool vx0 = (x0 >= 0) && (x0 < W);
        const bool vx1 = (x0 + 1 >= 0) && (x0 + 1 < W);
        const bool vy0 = (y0 >= 0) && (y0 < H);
        const bool vy1 = (y0 + 1 >= 0) && (y0 + 1 < H);

        const int pbase = b * LV + St[l];
        const int hoff  = h * CC;

        // byte offsets into fp16 buffer (element * 2)
        const int i00 = ((pbase + y0 * W + x0) * DD + hoff) << 1;
        const int i10 = i00 + (DD << 1);
        const int i01 = i00 + (W * DD << 1);
        const int i11 = i01 + (DD << 1);

        swo[t][0] = make_float2((vx0 && vy0) ? w00 : 0.f, __int_as_float((vx0 && vy0) ? i00 : 0));
        swo[t][1] = make_float2((vx1 && vy0) ? w10 : 0.f, __int_as_float((vx1 && vy0) ? i10 : 0));
        swo[t][2] = make_float2((vx0 && vy1) ? w01 : 0.f, __int_as_float((vx0 && vy1) ? i01 : 0));
        swo[t][3] = make_float2((vx1 && vy1) ? w11 : 0.f, __int_as_float((vx1 && vy1) ? i11 : 0));
    }
    __syncthreads();

    const int h    = tid >> 5;
    const int lane = tid & 31;
    const char* base = (const char*)g_vph + (lane << 1);
    float acc = 0.f;
#pragma unroll
    for (int i = 0; i < 16; i++) {
        const int t = h * 16 + i;
        float4 p01 = *(const float4*)(&swo[t][0]);
        float4 p23 = *(const float4*)(&swo[t][2]);
        acc = fmaf(p01.x, __half2float(*(const __half*)(base + __float_as_int(p01.y))), acc);
        acc = fmaf(p01.z, __half2float(*(const __half*)(base + __float_as_int(p01.w))), acc);
        acc = fmaf(p23.x, __half2float(*(const __half*)(base + __float_as_int(p23.y))), acc);
        acc = fmaf(p23.z, __half2float(*(const __half*)(base + __float_as_int(p23.w))), acc);
    }
    g_tmph[(size_t)bq * DD + h * CC + lane] = __float2half(acc);
}

// ---------------------------------------------------------------------------
extern "C" void kernel_launch(void* const* d_in, const int* in_sizes, int n_in,
                              void* d_out, int out_size)
{
    const float* query  = (const float*)d_in[0];
    const float* refpts = (const float*)d_in[1];
    const float* value  = (const float*)d_in[2];
    const float* w_off  = (const float*)d_in[3];
    const float* b_off  = (const float*)d_in[4];
    const float* w_attn = (const float*)d_in[5];
    const float* b_attn = (const float*)d_in[6];
    const float* w_v    = (const float*)d_in[7];
    const float* b_v    = (const float*)d_in[8];
    const float* w_o    = (const float*)d_in[9];
    const float* b_o    = (const float*)d_in[10];
    float* out = (float*)d_out;

    __half *vh, *qh, *vph, *tmph, *wvT, *woffT, *wattnT, *woT;
    float *offp, *attnp;
    cudaGetSymbolAddress((void**)&vh,    g_vh);
    cudaGetSymbolAddress((void**)&qh,    g_qh);
    cudaGetSymbolAddress((void**)&vph,   g_vph);
    cudaGetSymbolAddress((void**)&tmph,  g_tmph);
    cudaGetSymbolAddress((void**)&offp,  g_off);
    cudaGetSymbolAddress((void**)&attnp, g_attn);
    cudaGetSymbolAddress((void**)&wvT,   g_wvT);
    cudaGetSymbolAddress((void**)&woffT, g_woffT);
    cudaGetSymbolAddress((void**)&wattnT,g_wattnT);
    cudaGetSymbolAddress((void**)&woT,   g_woT);

    const int Mq = BS * LQ;      // 8000
    const int Mv = BS * LV;      // 68000

    // input conversions
    f32_to_f16<<<(Mv * DD) / 1024, 256>>>(value, vh, Mv * DD);
    f32_to_f16<<<(Mq * DD) / 1024, 256>>>(query, qh, Mq * DD);
    {
        dim3 blk(32, 8);
        transpose_w_h<<<dim3(DD / 32, DD / 32), blk>>>(w_v,    wvT,    DD);
        transpose_w_h<<<dim3(DD / 32, DD / 32), blk>>>(w_off,  woffT,  DD);
        transpose_w_h<<<dim3(128 / 32, DD / 32), blk>>>(w_attn, wattnT, 128);
        transpose_w_h<<<dim3(DD / 32, DD / 32), blk>>>(w_o,    woT,    DD);
    }

    // K1: Vp = value @ w_v + b_v  -> fp16
    gemm_h16<<<dim3((Mv + 127) / 128, 2), 256>>>(vh, wvT, b_v, nullptr, vph, Mv, DD);
    // K2a: off = query @ w_off + b_off -> fp32
    gemm_h16<<<dim3((Mq + 127) / 128, 2), 256>>>(qh, woffT, b_off, offp, nullptr, Mq, DD);
    // K2b: attn logits -> fp32
    gemm_h16<<<dim3((Mq + 127) / 128, 1), 256>>>(qh, wattnT, b_attn, attnp, nullptr, Mq, 128);
    // K3: softmax + sampling + aggregation -> fp16
    sample_agg_kernel<<<Mq, 256>>>(refpts);
    // K4: out = tmp @ w_o + b_o -> fp32
    gemm_h16<<<dim3((Mq + 127) / 128, 2), 256>>>(tmph, woT, b_o, out, nullptr, Mq, DD);
}

// round 10
// speedup vs baseline: 3.7828x; 1.1314x over previous
#include <cuda_runtime.h>
#include <cuda_fp16.h>
#include <cstdint>
#include <math.h>

#define BS 8
#define LQ 1000
#define DD 256
#define NH 8
#define NL 4
#define NP 4
#define CC 32
#define LV 8500   // 80*80 + 40*40 + 20*20 + 10*10

// ---------------- scratch (static device globals; no dynamic alloc) --------
__device__ __align__(16) __half g_vph [(size_t)BS * LV * DD];   // projected value fp16
__device__ __align__(16) float  g_off [(size_t)BS * LQ * DD];
__device__ __align__(16) float  g_attn[(size_t)BS * LQ * NH * NL * NP];
__device__ __align__(16) float  g_tmp [(size_t)BS * LQ * DD];   // aggregated fp32
__device__ __align__(16) __half g_wvT  [DD * DD];               // [N][K] fp16
__device__ __align__(16) __half g_woffT[DD * DD];
__device__ __align__(16) __half g_wattnT[(NH*NL*NP) * DD];
__device__ __align__(16) __half g_woT  [DD * DD];

// ======================= helpers ===========================================
__device__ __forceinline__ void cpasync16(uint32_t dst, const void* src) {
    asm volatile("cp.async.cg.shared.global [%0], [%1], 16;" :: "r"(dst), "l"(src));
}
__device__ __forceinline__ void cp_commit() { asm volatile("cp.async.commit_group;"); }

__device__ __forceinline__ uint32_t ld2cvt(const float* p) {
    float2 f = *(const float2*)p;
    __half2 h = __floats2half2_rn(f.x, f.y);
    return *(uint32_t*)&h;
}

// ====== tensor-core GEMM: C = A(Mx256, fp32) @ BT^T(fp16) + bias ===========
// A: [M][256] fp32, BT: [N][256] fp16 (K-major). Block tile 128x128, BK=32.
// 256 threads = 8 warps (4 M x 2 N), warp tile 32x64, m16n8k16, fp32 accum.
// A converted fp32->fp16 at fragment-load time.
#define LDA 36   // A smem row stride in floats (32 data + 4 pad) = 144 B
#define LDB 40   // B smem row stride in halves (32 data + 8 pad) = 80 B
#define SMEM_A_BYTES (2 * 128 * LDA * 4)          // 36864
#define SMEM_B_BYTES (2 * 128 * LDB * 2)          // 20480
#define SMEM_GEMM    (SMEM_A_BYTES + SMEM_B_BYTES) // 57344

__global__ __launch_bounds__(256)
void gemm_f32a(const float* __restrict__ A, const __half* __restrict__ BT,
               const float* __restrict__ bias, float* __restrict__ Cf,
               __half* __restrict__ Ch, int M, int N)
{
    extern __shared__ __align__(16) char smem[];
    float*  As = (float*)smem;                         // [2][128][LDA]
    __half* Bs = (__half*)(smem + SMEM_A_BYTES);       // [2][128][LDB]

    const int tid  = threadIdx.x;
    const int wid  = tid >> 5;
    const int lane = tid & 31;
    const int wm   = (wid & 3) * 32;
    const int wn   = (wid >> 2) * 64;
    const int grp  = lane >> 2;
    const int tig  = lane & 3;

    const int brow = blockIdx.x * 128;
    const int ncol = blockIdx.y * 128;

    float acc[2][8][4];
#pragma unroll
    for (int i = 0; i < 2; i++)
#pragma unroll
        for (int j = 0; j < 8; j++)
#pragma unroll
            for (int r = 0; r < 4; r++) acc[i][j][r] = 0.f;

    auto load = [&](int kb, int buf) {
#pragma unroll
        for (int t = 0; t < 4; t++) {
            const int lin = tid + t * 256;
            const int row = lin >> 3;
            const int c   = lin & 7;
            const float* sa = A + (size_t)min(brow + row, M - 1) * 256 + kb + c * 4;
            cpasync16((uint32_t)__cvta_generic_to_shared(&As[buf * 128 * LDA + row * LDA + c * 4]), sa);
        }
#pragma unroll
        for (int t = 0; t < 2; t++) {
            const int lin = tid + t * 256;
            const int row = lin >> 2;
            const int c   = lin & 3;
            const __half* sb = BT + (size_t)(ncol + row) * 256 + kb + c * 8;
            cpasync16((uint32_t)__cvta_generic_to_shared(&Bs[buf * 128 * LDB + row * LDB + c * 8]), sb);
        }
        cp_commit();
    };

    load(0, 0);

    for (int it = 0; it < 8; it++) {
        const int buf = it & 1;
        if (it + 1 < 8) {
            load((it + 1) * 32, buf ^ 1);
            asm volatile("cp.async.wait_group 1;");
        } else {
            asm volatile("cp.async.wait_group 0;");
        }
        __syncthreads();

        const float*  Ab = As + buf * 128 * LDA;
        const __half* Bb = Bs + buf * 128 * LDB;

#pragma unroll
        for (int ks = 0; ks < 2; ks++) {
            const int kh = ks * 16;
            uint32_t af[2][4];
#pragma unroll
            for (int mi = 0; mi < 2; mi++) {
                const int r0 = wm + mi * 16 + grp;
                af[mi][0] = ld2cvt(Ab + (r0    ) * LDA + kh + tig * 2);
                af[mi][1] = ld2cvt(Ab + (r0 + 8) * LDA + kh + tig * 2);
                af[mi][2] = ld2cvt(Ab + (r0    ) * LDA + kh + tig * 2 + 8);
                af[mi][3] = ld2cvt(Ab + (r0 + 8) * LDA + kh + tig * 2 + 8);
            }
#pragma unroll
            for (int j = 0; j < 8; j++) {
                const int nr = wn + j * 8 + grp;
                uint32_t b0 = *(const uint32_t*)&Bb[nr * LDB + kh + tig * 2];
                uint32_t b1 = *(const uint32_t*)&Bb[nr * LDB + kh + tig * 2 + 8];
#pragma unroll
                for (int mi = 0; mi < 2; mi++) {
                    asm volatile(
                        "mma.sync.aligned.m16n8k16.row.col.f32.f16.f16.f32 "
                        "{%0,%1,%2,%3}, {%4,%5,%6,%7}, {%8,%9}, {%0,%1,%2,%3};"
                        : "+f"(acc[mi][j][0]), "+f"(acc[mi][j][1]),
                          "+f"(acc[mi][j][2]), "+f"(acc[mi][j][3])
                        : "r"(af[mi][0]), "r"(af[mi][1]),
                          "r"(af[mi][2]), "r"(af[mi][3]),
                          "r"(b0), "r"(b1));
                }
            }
        }
        __syncthreads();
    }

    // ---- epilogue ----
#pragma unroll
    for (int mi = 0; mi < 2; mi++) {
#pragma unroll
        for (int j = 0; j < 8; j++) {
            const int col = ncol + wn + j * 8 + 2 * tig;
            const float bx = bias[col], by = bias[col + 1];
            const int r0 = brow + wm + mi * 16 + grp;
            const int r1 = r0 + 8;
            if (Ch) {
                if (r0 < M)
                    *(__half2*)(Ch + (size_t)r0 * N + col) =
                        __floats2half2_rn(acc[mi][j][0] + bx, acc[mi][j][1] + by);
                if (r1 < M)
                    *(__half2*)(Ch + (size_t)r1 * N + col) =
                        __floats2half2_rn(acc[mi][j][2] + bx, acc[mi][j][3] + by);
            } else {
                if (r0 < M)
                    *(float2*)(Cf + (size_t)r0 * N + col) =
                        make_float2(acc[mi][j][0] + bx, acc[mi][j][1] + by);
                if (r1 < M)
                    *(float2*)(Cf + (size_t)r1 * N + col) =
                        make_float2(acc[mi][j][2] + bx, acc[mi][j][3] + by);
            }
        }
    }
}

// ========= fused transpose+convert of all 4 weights (one launch) ===========
__global__ void transpose_all(const float* __restrict__ w_v,
                              const float* __restrict__ w_off,
                              const float* __restrict__ w_attn,
                              const float* __restrict__ w_o,
                              __half* __restrict__ wvT,
                              __half* __restrict__ woffT,
                              __half* __restrict__ wattnT,
                              __half* __restrict__ woT)
{
    const int z = blockIdx.z;
    const float* src = (z == 0) ? w_v : (z == 1) ? w_off : (z == 2) ? w_attn : w_o;
    __half* dst      = (z == 0) ? wvT : (z == 1) ? woffT : (z == 2) ? wattnT : woT;
    const int N = (z == 2) ? 128 : 256;
    if (blockIdx.x * 32 >= N) return;

    __shared__ float t[32][33];
    const int n0 = blockIdx.x * 32;
    const int k0 = blockIdx.y * 32;
    const int x = threadIdx.x, y = threadIdx.y;   // 32 x 8
#pragma unroll
    for (int i = 0; i < 32; i += 8)
        t[y + i][x] = src[(size_t)(k0 + y + i) * N + n0 + x];
    __syncthreads();
#pragma unroll
    for (int i = 0; i < 32; i += 8)
        dst[(size_t)(n0 + y + i) * 256 + k0 + x] = __float2half(t[x][y + i]);
}

// ---------------- fused softmax + bilinear sampling + aggregation ----------
// Phase 1: 128 threads, one per (h,l,p) point -> weights + byte offsets.
// Phase 2: 8 warps (heads); lanes split into 2 half-warps of 16 lanes.
// Each half-warp handles a disjoint half of the 16 points; each lane owns a
// __half2 channel pair. Partial sums combined across half-warps via shfl_xor.
__global__ __launch_bounds__(256)
void sample_agg_kernel(const float* __restrict__ ref)
{
    __shared__ __align__(16) float2 swo[128][4];   // .x weight, .y byte offset

    const int bq  = blockIdx.x;
    const int b   = bq / LQ;
    const int tid = threadIdx.x;

    const int Wl[NL] = {80, 40, 20, 10};
    const int St[NL] = {0, 6400, 8000, 8400};

    if (tid < 128) {
        const int t = tid;
        const int h = t >> 4;
        const int i = t & 15;
        const int l = i >> 2;

        float logit = g_attn[(size_t)bq * 128 + t];
        float m = logit;
#pragma unroll
        for (int d = 8; d; d >>= 1) m = fmaxf(m, __shfl_xor_sync(0xffffffffu, m, d, 16));
        float e = __expf(logit - m);
        float s = e;
#pragma unroll
        for (int d = 8; d; d >>= 1) s += __shfl_xor_sync(0xffffffffu, s, d, 16);
        const float aw = e / s;

        const float ox = g_off[(size_t)bq * DD + 2 * t];
        const float oy = g_off[(size_t)bq * DD + 2 * t + 1];
        const float rx = ref[((size_t)bq * NL + l) * 2 + 0];
        const float ry = ref[((size_t)bq * NL + l) * 2 + 1];

        const int   W = Wl[l], H = Wl[l];
        const float Wf = (float)W;

        const float x = fmaf(rx, Wf, ox) - 0.5f;
        const float y = fmaf(ry, Wf, oy) - 0.5f;
        const float x0f = floorf(x), y0f = floorf(y);
        const int   x0 = (int)x0f,  y0 = (int)y0f;
        const float fx = x - x0f,   fy = y - y0f;

        const float w00 = (1.f - fx) * (1.f - fy) * aw;
        const float w10 = fx * (1.f - fy) * aw;
        const float w01 = (1.f - fx) * fy * aw;
        const float w11 = fx * fy * aw;

        const bool vx0 = (x0 >= 0) && (x0 < W);
        const bool vx1 = (x0 + 1 >= 0) && (x0 + 1 < W);
        const bool vy0 = (y0 >= 0) && (y0 < H);
        const bool vy1 = (y0 + 1 >= 0) && (y0 + 1 < H);

        const int pbase = b * LV + St[l];
        const int hoff  = h * CC;

        // byte offsets into fp16 buffer (element * 2)
        const int i00 = ((pbase + y0 * W + x0) * DD + hoff) << 1;
        const int i10 = i00 + (DD << 1);
        const int i01 = i00 + (W * DD << 1);
        const int i11 = i01 + (DD << 1);

        swo[t][0] = make_float2((vx0 && vy0) ? w00 : 0.f, __int_as_float((vx0 && vy0) ? i00 : 0));
        swo[t][1] = make_float2((vx1 && vy0) ? w10 : 0.f, __int_as_float((vx1 && vy0) ? i10 : 0));
        swo[t][2] = make_float2((vx0 && vy1) ? w01 : 0.f, __int_as_float((vx0 && vy1) ? i01 : 0));
        swo[t][3] = make_float2((vx1 && vy1) ? w11 : 0.f, __int_as_float((vx1 && vy1) ? i11 : 0));
    }
    __syncthreads();

    const int h    = tid >> 5;
    const int lane = tid & 31;
    const int lh   = lane >> 4;          // which half of the points
    const int ch   = (lane & 15) * 2;    // channel pair
    const char* base = (const char*)g_vph + (ch << 1);

    float accx = 0.f, accy = 0.f;
#pragma unroll
    for (int i = 0; i < 8; i++) {
        const int t = h * 16 + i * 2 + lh;
        float4 p01 = *(const float4*)(&swo[t][0]);
        float4 p23 = *(const float4*)(&swo[t][2]);
#pragma unroll
        for (int c = 0; c < 4; c++) {
            const float w   = (c == 0) ? p01.x : (c == 1) ? p01.z : (c == 2) ? p23.x : p23.z;
            const float off = (c == 0) ? p01.y : (c == 1) ? p01.w : (c == 2) ? p23.y : p23.w;
            const __half2 v = *(const __half2*)(base + __float_as_int(off));
            const float2 f  = __half22float2(v);
            accx = fmaf(w, f.x, accx);
            accy = fmaf(w, f.y, accy);
        }
    }
    // combine the two half-warps' partial sums (points split across lh)
    accx += __shfl_xor_sync(0xffffffffu, accx, 16);
    accy += __shfl_xor_sync(0xffffffffu, accy, 16);
    if (lh == 0)
        *(float2*)(g_tmp + (size_t)bq * DD + h * CC + ch) = make_float2(accx, accy);
}

// ---------------------------------------------------------------------------
extern "C" void kernel_launch(void* const* d_in, const int* in_sizes, int n_in,
                              void* d_out, int out_size)
{
    const float* query  = (const float*)d_in[0];
    const float* refpts = (const float*)d_in[1];
    const float* value  = (const float*)d_in[2];
    const float* w_off  = (const float*)d_in[3];
    const float* b_off  = (const float*)d_in[4];
    const float* w_attn = (const float*)d_in[5];
    const float* b_attn = (const float*)d_in[6];
    const float* w_v    = (const float*)d_in[7];
    const float* b_v    = (const float*)d_in[8];
    const float* w_o    = (const float*)d_in[9];
    const float* b_o    = (const float*)d_in[10];
    float* out = (float*)d_out;

    __half *vph, *wvT, *woffT, *wattnT, *woT;
    float *offp, *attnp, *tmpp;
    cudaGetSymbolAddress((void**)&vph,   g_vph);
    cudaGetSymbolAddress((void**)&offp,  g_off);
    cudaGetSymbolAddress((void**)&attnp, g_attn);
    cudaGetSymbolAddress((void**)&tmpp,  g_tmp);
    cudaGetSymbolAddress((void**)&wvT,   g_wvT);
    cudaGetSymbolAddress((void**)&woffT, g_woffT);
    cudaGetSymbolAddress((void**)&wattnT,g_wattnT);
    cudaGetSymbolAddress((void**)&woT,   g_woT);

    cudaFuncSetAttribute(gemm_f32a, cudaFuncAttributeMaxDynamicSharedMemorySize, SMEM_GEMM);

    const int Mq = BS * LQ;      // 8000
    const int Mv = BS * LV;      // 68000

    // fused weight transposes (one launch)
    transpose_all<<<dim3(8, 8, 4), dim3(32, 8)>>>(w_v, w_off, w_attn, w_o,
                                                  wvT, woffT, wattnT, woT);

    // K1: Vp = value @ w_v + b_v  -> fp16
    gemm_f32a<<<dim3((Mv + 127) / 128, 2), 256, SMEM_GEMM>>>(value, wvT, b_v, nullptr, vph, Mv, DD);
    // K2a: off = query @ w_off + b_off -> fp32
    gemm_f32a<<<dim3((Mq + 127) / 128, 2), 256, SMEM_GEMM>>>(query, woffT, b_off, offp, nullptr, Mq, DD);
    // K2b: attn logits -> fp32
    gemm_f32a<<<dim3((Mq + 127) / 128, 1), 256, SMEM_GEMM>>>(query, wattnT, b_attn, attnp, nullptr, Mq, 128);
    // K3: softmax + sampling + aggregation -> fp32
    sample_agg_kernel<<<Mq, 256>>>(refpts);
    // K4: out = tmp @ w_o + b_o -> fp32
    gemm_f32a<<<dim3((Mq + 127) / 128, 2), 256, SMEM_GEMM>>>(tmpp, woT, b_o, out, nullptr, Mq, DD);
}

// round 11
// speedup vs baseline: 3.9759x; 1.0511x over previous
#include <cuda_runtime.h>
#include <cuda_fp16.h>
#include <cstdint>
#include <math.h>

#define BS 8
#define LQ 1000
#define DD 256
#define NH 8
#define NL 4
#define NP 4
#define CC 32
#define LV 8500   // 80*80 + 40*40 + 20*20 + 10*10

// ---------------- scratch (static device globals; no dynamic alloc) --------
__device__ __align__(16) __half g_vph [(size_t)BS * LV * DD];   // projected value fp16
__device__ __align__(16) float  g_offattn[(size_t)BS * LQ * 384]; // off(256) | attn(128)
__device__ __align__(16) float  g_tmp [(size_t)BS * LQ * DD];   // aggregated fp32
__device__ __align__(16) __half g_wvT [DD * DD];                // [N][K] fp16
__device__ __align__(16) __half g_wqT [384 * DD];               // [w_off^T ; w_attn^T]
__device__ __align__(16) float  g_bq  [384];                    // b_off | b_attn
__device__ __align__(16) __half g_woT [DD * DD];

// ======================= helpers ===========================================
__device__ __forceinline__ void cpasync16(uint32_t dst, const void* src) {
    asm volatile("cp.async.cg.shared.global [%0], [%1], 16;" :: "r"(dst), "l"(src));
}
__device__ __forceinline__ void cp_commit() { asm volatile("cp.async.commit_group;"); }

__device__ __forceinline__ uint32_t ld2cvt(const float* p) {
    float2 f = *(const float2*)p;
    __half2 h = __floats2half2_rn(f.x, f.y);
    return *(uint32_t*)&h;
}

// ====== tensor-core GEMM: C = A(Mx256, fp32) @ BT^T(fp16) + bias ===========
// A: [M][256] fp32, BT: [N][256] fp16 (K-major). Block tile 128x128, BK=32,
// 3-stage cp.async pipeline. 256 threads = 8 warps (4M x 2N), warp 32x64,
// m16n8k16, fp32 accumulate. A converted fp32->fp16 at fragment-load time.
#define LDA 36   // A smem row stride (floats)
#define LDB 40   // B smem row stride (halves)
#define STG_A (128 * LDA)                    // floats per stage
#define STG_B (128 * LDB)                    // halves per stage
#define SMEM_A_BYTES (3 * STG_A * 4)         // 55296
#define SMEM_GEMM    (SMEM_A_BYTES + 3 * STG_B * 2)   // 86016

__global__ __launch_bounds__(256)
void gemm_f32a(const float* __restrict__ A, const __half* __restrict__ BT,
               const float* __restrict__ bias, float* __restrict__ Cf,
               __half* __restrict__ Ch, int M, int N)
{
    extern __shared__ __align__(16) char smem[];
    float*  As = (float*)smem;                         // [3][128][LDA]
    __half* Bs = (__half*)(smem + SMEM_A_BYTES);       // [3][128][LDB]

    const int tid  = threadIdx.x;
    const int wid  = tid >> 5;
    const int lane = tid & 31;
    const int wm   = (wid & 3) * 32;
    const int wn   = (wid >> 2) * 64;
    const int grp  = lane >> 2;
    const int tig  = lane & 3;

    const int brow = blockIdx.x * 128;
    const int ncol = blockIdx.y * 128;

    float acc[2][8][4];
#pragma unroll
    for (int i = 0; i < 2; i++)
#pragma unroll
        for (int j = 0; j < 8; j++)
#pragma unroll
            for (int r = 0; r < 4; r++) acc[i][j][r] = 0.f;

    auto load = [&](int kb, int stg) {
#pragma unroll
        for (int t = 0; t < 4; t++) {
            const int lin = tid + t * 256;
            const int row = lin >> 3;
            const int c   = lin & 7;
            const float* sa = A + (size_t)min(brow + row, M - 1) * 256 + kb + c * 4;
            cpasync16((uint32_t)__cvta_generic_to_shared(&As[stg * STG_A + row * LDA + c * 4]), sa);
        }
#pragma unroll
        for (int t = 0; t < 2; t++) {
            const int lin = tid + t * 256;
            const int row = lin >> 2;
            const int c   = lin & 3;
            const __half* sb = BT + (size_t)(ncol + row) * 256 + kb + c * 8;
            cpasync16((uint32_t)__cvta_generic_to_shared(&Bs[stg * STG_B + row * LDB + c * 8]), sb);
        }
        cp_commit();
    };

    load(0, 0);
    load(32, 1);

    for (int it = 0; it < 8; it++) {
        const int buf = it % 3;
        if (it + 2 < 8) load((it + 2) * 32, (it + 2) % 3);
        if (it < 6)       asm volatile("cp.async.wait_group 2;");
        else if (it == 6) asm volatile("cp.async.wait_group 1;");
        else              asm volatile("cp.async.wait_group 0;");
        __syncthreads();

        const float*  Ab = As + buf * STG_A;
        const __half* Bb = Bs + buf * STG_B;

#pragma unroll
        for (int ks = 0; ks < 2; ks++) {
            const int kh = ks * 16;
            uint32_t af[2][4];
#pragma unroll
            for (int mi = 0; mi < 2; mi++) {
                const int r0 = wm + mi * 16 + grp;
                af[mi][0] = ld2cvt(Ab + (r0    ) * LDA + kh + tig * 2);
                af[mi][1] = ld2cvt(Ab + (r0 + 8) * LDA + kh + tig * 2);
                af[mi][2] = ld2cvt(Ab + (r0    ) * LDA + kh + tig * 2 + 8);
                af[mi][3] = ld2cvt(Ab + (r0 + 8) * LDA + kh + tig * 2 + 8);
            }
#pragma unroll
            for (int j = 0; j < 8; j++) {
                const int nr = wn + j * 8 + grp;
                uint32_t b0 = *(const uint32_t*)&Bb[nr * LDB + kh + tig * 2];
                uint32_t b1 = *(const uint32_t*)&Bb[nr * LDB + kh + tig * 2 + 8];
#pragma unroll
                for (int mi = 0; mi < 2; mi++) {
                    asm volatile(
                        "mma.sync.aligned.m16n8k16.row.col.f32.f16.f16.f32 "
                        "{%0,%1,%2,%3}, {%4,%5,%6,%7}, {%8,%9}, {%0,%1,%2,%3};"
                        : "+f"(acc[mi][j][0]), "+f"(acc[mi][j][1]),
                          "+f"(acc[mi][j][2]), "+f"(acc[mi][j][3])
                        : "r"(af[mi][0]), "r"(af[mi][1]),
                          "r"(af[mi][2]), "r"(af[mi][3]),
                          "r"(b0), "r"(b1));
                }
            }
        }
        __syncthreads();
    }

    // ---- epilogue ----
#pragma unroll
    for (int mi = 0; mi < 2; mi++) {
#pragma unroll
        for (int j = 0; j < 8; j++) {
            const int col = ncol + wn + j * 8 + 2 * tig;
            const float bx = bias[col], by = bias[col + 1];
            const int r0 = brow + wm + mi * 16 + grp;
            const int r1 = r0 + 8;
            if (Ch) {
                if (r0 < M)
                    *(__half2*)(Ch + (size_t)r0 * N + col) =
                        __floats2half2_rn(acc[mi][j][0] + bx, acc[mi][j][1] + by);
                if (r1 < M)
                    *(__half2*)(Ch + (size_t)r1 * N + col) =
                        __floats2half2_rn(acc[mi][j][2] + bx, acc[mi][j][3] + by);
            } else {
                if (r0 < M)
                    *(float2*)(Cf + (size_t)r0 * N + col) =
                        make_float2(acc[mi][j][0] + bx, acc[mi][j][1] + by);
                if (r1 < M)
                    *(float2*)(Cf + (size_t)r1 * N + col) =
                        make_float2(acc[mi][j][2] + bx, acc[mi][j][3] + by);
            }
        }
    }
}

// ========= fused transpose+convert of all weights + bias pack ==============
// z=0: w_v -> wvT ; z=1: w_off -> wqT rows 0..255 ; z=2: w_attn -> wqT rows
// 256..383 ; z=3: w_o -> woT ; z=4: bias pack (block 0,0 only).
__global__ void transpose_all(const float* __restrict__ w_v,
                              const float* __restrict__ w_off,
                              const float* __restrict__ w_attn,
                              const float* __restrict__ w_o,
                              const float* __restrict__ b_off,
                              const float* __restrict__ b_attn,
                              __half* __restrict__ wvT,
                              __half* __restrict__ wqT,
                              __half* __restrict__ woT,
                              float* __restrict__ bq)
{
    const int z = blockIdx.z;
    const int tid = threadIdx.y * 32 + threadIdx.x;
    if (z == 4) {
        if (blockIdx.x == 0 && blockIdx.y == 0) {
            if (tid < 256) bq[tid] = b_off[tid];
            if (tid < 128) bq[256 + tid] = b_attn[tid];
        }
        return;
    }
    const float* src = (z == 0) ? w_v : (z == 1) ? w_off : (z == 2) ? w_attn : w_o;
    __half* dst      = (z == 0) ? wvT : (z == 1) ? wqT : (z == 2) ? (wqT + 256 * DD) : woT;
    const int N = (z == 2) ? 128 : 256;
    if (blockIdx.x * 32 >= N) return;

    __shared__ float t[32][33];
    const int n0 = blockIdx.x * 32;
    const int k0 = blockIdx.y * 32;
    const int x = threadIdx.x, y = threadIdx.y;   // 32 x 8
#pragma unroll
    for (int i = 0; i < 32; i += 8)
        t[y + i][x] = src[(size_t)(k0 + y + i) * N + n0 + x];
    __syncthreads();
#pragma unroll
    for (int i = 0; i < 32; i += 8)
        dst[(size_t)(n0 + y + i) * 256 + k0 + x] = __float2half(t[x][y + i]);
}

// ---------------- fused softmax + bilinear sampling + aggregation ----------
// Phase 1: 128 threads, one per (h,l,p) point -> weights + byte offsets.
// Phase 2: 8 warps (heads); 2 half-warps each take half the points; lane owns
// a __half2 channel pair; partials combined via shfl_xor(16).
__global__ __launch_bounds__(256)
void sample_agg_kernel(const float* __restrict__ ref)
{
    __shared__ __align__(16) float2 swo[128][4];   // .x weight, .y byte offset

    const int bq  = blockIdx.x;
    const int b   = bq / LQ;
    const int tid = threadIdx.x;

    const int Wl[NL] = {80, 40, 20, 10};
    const int St[NL] = {0, 6400, 8000, 8400};

    if (tid < 128) {
        const int t = tid;
        const int h = t >> 4;
        const int i = t & 15;
        const int l = i >> 2;

        float logit = g_offattn[(size_t)bq * 384 + 256 + t];
        float m = logit;
#pragma unroll
        for (int d = 8; d; d >>= 1) m = fmaxf(m, __shfl_xor_sync(0xffffffffu, m, d, 16));
        float e = __expf(logit - m);
        float s = e;
#pragma unroll
        for (int d = 8; d; d >>= 1) s += __shfl_xor_sync(0xffffffffu, s, d, 16);
        const float aw = e / s;

        const float ox = g_offattn[(size_t)bq * 384 + 2 * t];
        const float oy = g_offattn[(size_t)bq * 384 + 2 * t + 1];
        const float rx = ref[((size_t)bq * NL + l) * 2 + 0];
        const float ry = ref[((size_t)bq * NL + l) * 2 + 1];

        const int   W = Wl[l], H = Wl[l];
        const float Wf = (float)W;

        const float x = fmaf(rx, Wf, ox) - 0.5f;
        const float y = fmaf(ry, Wf, oy) - 0.5f;
        const float x0f = floorf(x), y0f = floorf(y);
        const int   x0 = (int)x0f,  y0 = (int)y0f;
        const float fx = x - x0f,   fy = y - y0f;

        const float w00 = (1.f - fx) * (1.f - fy) * aw;
        const float w10 = fx * (1.f - fy) * aw;
        const float w01 = (1.f - fx) * fy * aw;
        const float w11 = fx * fy * aw;

        const bool vx0 = (x0 >= 0) && (x0 < W);
        const bool vx1 = (x0 + 1 >= 0) && (x0 + 1 < W);
        const bool vy0 = (y0 >= 0) && (y0 < H);
        const bool vy1 = (y0 + 1 >= 0) && (y0 + 1 < H);

        const int pbase = b * LV + St[l];
        const int hoff  = h * CC;

        const int i00 = ((pbase + y0 * W + x0) * DD + hoff) << 1;   // fp16 byte offs
        const int i10 = i00 + (DD << 1);
        const int i01 = i00 + (W * DD << 1);
        const int i11 = i01 + (DD << 1);

        swo[t][0] = make_float2((vx0 && vy0) ? w00 : 0.f, __int_as_float((vx0 && vy0) ? i00 : 0));
        swo[t][1] = make_float2((vx1 && vy0) ? w10 : 0.f, __int_as_float((vx1 && vy0) ? i10 : 0));
        swo[t][2] = make_float2((vx0 && vy1) ? w01 : 0.f, __int_as_float((vx0 && vy1) ? i01 : 0));
        swo[t][3] = make_float2((vx1 && vy1) ? w11 : 0.f, __int_as_float((vx1 && vy1) ? i11 : 0));
    }
    __syncthreads();

    const int h    = tid >> 5;
    const int lane = tid & 31;
    const int lh   = lane >> 4;
    const int ch   = (lane & 15) * 2;
    const char* base = (const char*)g_vph + (ch << 1);

    float accx = 0.f, accy = 0.f;
#pragma unroll
    for (int i = 0; i < 8; i++) {
        const int t = h * 16 + i * 2 + lh;
        float4 p01 = *(const float4*)(&swo[t][0]);
        float4 p23 = *(const float4*)(&swo[t][2]);
#pragma unroll
        for (int c = 0; c < 4; c++) {
            const float w   = (c == 0) ? p01.x : (c == 1) ? p01.z : (c == 2) ? p23.x : p23.z;
            const float off = (c == 0) ? p01.y : (c == 1) ? p01.w : (c == 2) ? p23.y : p23.w;
            const __half2 v = *(const __half2*)(base + __float_as_int(off));
            const float2 f  = __half22float2(v);
            accx = fmaf(w, f.x, accx);
            accy = fmaf(w, f.y, accy);
        }
    }
    accx += __shfl_xor_sync(0xffffffffu, accx, 16);
    accy += __shfl_xor_sync(0xffffffffu, accy, 16);
    if (lh == 0)
        *(float2*)(g_tmp + (size_t)bq * DD + h * CC + ch) = make_float2(accx, accy);
}

// ---------------------------------------------------------------------------
extern "C" void kernel_launch(void* const* d_in, const int* in_sizes, int n_in,
                              void* d_out, int out_size)
{
    const float* query  = (const float*)d_in[0];
    const float* refpts = (const float*)d_in[1];
    const float* value  = (const float*)d_in[2];
    const float* w_off  = (const float*)d_in[3];
    const float* b_off  = (const float*)d_in[4];
    const float* w_attn = (const float*)d_in[5];
    const float* b_attn = (const float*)d_in[6];
    const float* w_v    = (const float*)d_in[7];
    const float* b_v    = (const float*)d_in[8];
    const float* w_o    = (const float*)d_in[9];
    const float* b_o    = (const float*)d_in[10];
    float* out = (float*)d_out;

    __half *vph, *wvT, *wqT, *woT;
    float *oap, *tmpp, *bqp;
    cudaGetSymbolAddress((void**)&vph,  g_vph);
    cudaGetSymbolAddress((void**)&oap,  g_offattn);
    cudaGetSymbolAddress((void**)&tmpp, g_tmp);
    cudaGetSymbolAddress((void**)&wvT,  g_wvT);
    cudaGetSymbolAddress((void**)&wqT,  g_wqT);
    cudaGetSymbolAddress((void**)&woT,  g_woT);
    cudaGetSymbolAddress((void**)&bqp,  g_bq);

    cudaFuncSetAttribute(gemm_f32a, cudaFuncAttributeMaxDynamicSharedMemorySize, SMEM_GEMM);

    const int Mq = BS * LQ;      // 8000
    const int Mv = BS * LV;      // 68000

    // fused weight transposes + bias pack (one launch)
    transpose_all<<<dim3(8, 8, 5), dim3(32, 8)>>>(w_v, w_off, w_attn, w_o,
                                                  b_off, b_attn,
                                                  wvT, wqT, woT, bqp);

    // K1: Vp = value @ w_v + b_v  -> fp16
    gemm_f32a<<<dim3((Mv + 127) / 128, 2), 256, SMEM_GEMM>>>(value, wvT, b_v, nullptr, vph, Mv, DD);
    // K2: [off | attn] = query @ [w_off | w_attn] + [b_off | b_attn] -> fp32, N=384
    gemm_f32a<<<dim3((Mq + 127) / 128, 3), 256, SMEM_GEMM>>>(query, wqT, bqp, oap, nullptr, Mq, 384);
    // K3: softmax + sampling + aggregation -> fp32
    sample_agg_kernel<<<Mq, 256>>>(refpts);
    // K4: out = tmp @ w_o + b_o -> fp32
    gemm_f32a<<<dim3((Mq + 127) / 128, 2), 256, SMEM_GEMM>>>(tmpp, woT, b_o, out, nullptr, Mq, DD);
}

// round 12
// speedup vs baseline: 4.2503x; 1.0690x over previous
#include <cuda_runtime.h>
#include <cuda_fp16.h>
#include <cstdint>
#include <math.h>

#define BS 8
#define LQ 1000
#define DD 256
#define NH 8
#define NL 4
#define NP 4
#define CC 32
#define LV 8500   // 80*80 + 40*40 + 20*20 + 10*10

// ---------------- scratch (static device globals; no dynamic alloc) --------
__device__ __align__(16) __half g_vph [(size_t)BS * LV * DD];   // projected value fp16
__device__ __align__(16) float  g_offattn[(size_t)BS * LQ * 384]; // off(256) | attn(128)
__device__ __align__(16) float  g_tmp [(size_t)BS * LQ * DD];   // aggregated fp32
__device__ __align__(16) __half g_wvT [DD * DD];                // [N][K] fp16
__device__ __align__(16) __half g_wqT [384 * DD];               // [w_off^T ; w_attn^T]
__device__ __align__(16) float  g_bq  [384];                    // b_off | b_attn
__device__ __align__(16) __half g_woT [DD * DD];

// ======================= helpers ===========================================
__device__ __forceinline__ void cpasync16(uint32_t dst, const void* src) {
    asm volatile("cp.async.cg.shared.global [%0], [%1], 16;" :: "r"(dst), "l"(src));
}
__device__ __forceinline__ void cp_commit() { asm volatile("cp.async.commit_group;"); }

__device__ __forceinline__ uint32_t ld2cvt(const float* p) {
    float2 f = *(const float2*)p;
    __half2 h = __floats2half2_rn(f.x, f.y);
    return *(uint32_t*)&h;
}

// ====== tensor-core GEMM body: C = A(Mx256, fp32) @ BT^T(fp16) + bias ======
// Block tile 128x128, BK=32, 3-stage cp.async pipeline, 256 thr = 8 warps,
// warp tile 32x64, m16n8k16, fp32 accumulate.
#define LDA 36
#define LDB 40
#define STG_A (128 * LDA)
#define STG_B (128 * LDB)
#define SMEM_A_BYTES (3 * STG_A * 4)                   // 55296
#define SMEM_GEMM    (SMEM_A_BYTES + 3 * STG_B * 2)    // 86016

__device__ __forceinline__
void gemm_body(const float* __restrict__ A, const __half* __restrict__ BT,
               const float* __restrict__ bias, float* __restrict__ Cf,
               __half* __restrict__ Ch, int M, int N, int brow, int ncol)
{
    extern __shared__ __align__(16) char smem[];
    float*  As = (float*)smem;
    __half* Bs = (__half*)(smem + SMEM_A_BYTES);

    const int tid  = threadIdx.x;
    const int wid  = tid >> 5;
    const int lane = tid & 31;
    const int wm   = (wid & 3) * 32;
    const int wn   = (wid >> 2) * 64;
    const int grp  = lane >> 2;
    const int tig  = lane & 3;

    float acc[2][8][4];
#pragma unroll
    for (int i = 0; i < 2; i++)
#pragma unroll
        for (int j = 0; j < 8; j++)
#pragma unroll
            for (int r = 0; r < 4; r++) acc[i][j][r] = 0.f;

    auto load = [&](int kb, int stg) {
#pragma unroll
        for (int t = 0; t < 4; t++) {
            const int lin = tid + t * 256;
            const int row = lin >> 3;
            const int c   = lin & 7;
            const float* sa = A + (size_t)min(brow + row, M - 1) * 256 + kb + c * 4;
            cpasync16((uint32_t)__cvta_generic_to_shared(&As[stg * STG_A + row * LDA + c * 4]), sa);
        }
#pragma unroll
        for (int t = 0; t < 2; t++) {
            const int lin = tid + t * 256;
            const int row = lin >> 2;
            const int c   = lin & 3;
            const __half* sb = BT + (size_t)(ncol + row) * 256 + kb + c * 8;
            cpasync16((uint32_t)__cvta_generic_to_shared(&Bs[stg * STG_B + row * LDB + c * 8]), sb);
        }
        cp_commit();
    };

    load(0, 0);
    load(32, 1);

    for (int it = 0; it < 8; it++) {
        const int buf = it % 3;
        if (it + 2 < 8) load((it + 2) * 32, (it + 2) % 3);
        if (it < 6)       asm volatile("cp.async.wait_group 2;");
        else if (it == 6) asm volatile("cp.async.wait_group 1;");
        else              asm volatile("cp.async.wait_group 0;");
        __syncthreads();

        const float*  Ab = As + buf * STG_A;
        const __half* Bb = Bs + buf * STG_B;

#pragma unroll
        for (int ks = 0; ks < 2; ks++) {
            const int kh = ks * 16;
            uint32_t af[2][4];
#pragma unroll
            for (int mi = 0; mi < 2; mi++) {
                const int r0 = wm + mi * 16 + grp;
                af[mi][0] = ld2cvt(Ab + (r0    ) * LDA + kh + tig * 2);
                af[mi][1] = ld2cvt(Ab + (r0 + 8) * LDA + kh + tig * 2);
                af[mi][2] = ld2cvt(Ab + (r0    ) * LDA + kh + tig * 2 + 8);
                af[mi][3] = ld2cvt(Ab + (r0 + 8) * LDA + kh + tig * 2 + 8);
            }
#pragma unroll
            for (int j = 0; j < 8; j++) {
                const int nr = wn + j * 8 + grp;
                uint32_t b0 = *(const uint32_t*)&Bb[nr * LDB + kh + tig * 2];
                uint32_t b1 = *(const uint32_t*)&Bb[nr * LDB + kh + tig * 2 + 8];
#pragma unroll
                for (int mi = 0; mi < 2; mi++) {
                    asm volatile(
                        "mma.sync.aligned.m16n8k16.row.col.f32.f16.f16.f32 "
                        "{%0,%1,%2,%3}, {%4,%5,%6,%7}, {%8,%9}, {%0,%1,%2,%3};"
                        : "+f"(acc[mi][j][0]), "+f"(acc[mi][j][1]),
                          "+f"(acc[mi][j][2]), "+f"(acc[mi][j][3])
                        : "r"(af[mi][0]), "r"(af[mi][1]),
                          "r"(af[mi][2]), "r"(af[mi][3]),
                          "r"(b0), "r"(b1));
                }
            }
        }
        __syncthreads();
    }

#pragma unroll
    for (int mi = 0; mi < 2; mi++) {
#pragma unroll
        for (int j = 0; j < 8; j++) {
            const int col = ncol + wn + j * 8 + 2 * tig;
            const float bx = bias[col], by = bias[col + 1];
            const int r0 = brow + wm + mi * 16 + grp;
            const int r1 = r0 + 8;
            if (Ch) {
                if (r0 < M)
                    *(__half2*)(Ch + (size_t)r0 * N + col) =
                        __floats2half2_rn(acc[mi][j][0] + bx, acc[mi][j][1] + by);
                if (r1 < M)
                    *(__half2*)(Ch + (size_t)r1 * N + col) =
                        __floats2half2_rn(acc[mi][j][2] + bx, acc[mi][j][3] + by);
            } else {
                if (r0 < M)
                    *(float2*)(Cf + (size_t)r0 * N + col) =
                        make_float2(acc[mi][j][0] + bx, acc[mi][j][1] + by);
                if (r1 < M)
                    *(float2*)(Cf + (size_t)r1 * N + col) =
                        make_float2(acc[mi][j][2] + bx, acc[mi][j][3] + by);
            }
        }
    }
}

// ---- fused K1+K2: one launch, flattened grid; K2's blocks scheduled first --
#define K1_TX 532                       // ceil(68000/128)
#define K2_TX 63                        // ceil(8000/128)
#define K2_BLOCKS (K2_TX * 3)           // N=384 -> 3 col tiles
#define K1_BLOCKS (K1_TX * 2)           // N=256 -> 2 col tiles

__global__ __launch_bounds__(256, 2)
void gemm_fused(const float* __restrict__ value, const float* __restrict__ query,
                const float* __restrict__ b_v)
{
    const int bid = blockIdx.x;
    if (bid < K2_BLOCKS) {
        const int bx = bid % K2_TX, by = bid / K2_TX;
        gemm_body(query, g_wqT, g_bq, g_offattn, nullptr,
                  BS * LQ, 384, bx * 128, by * 128);
    } else {
        const int r = bid - K2_BLOCKS;
        const int bx = r % K1_TX, by = r / K1_TX;
        gemm_body(value, g_wvT, b_v, nullptr, g_vph,
                  BS * LV, 256, bx * 128, by * 128);
    }
}

// ---- K4 standalone -----------------------------------------------------
__global__ __launch_bounds__(256, 2)
void gemm_k4(const float* __restrict__ b_o, float* __restrict__ out)
{
    gemm_body(g_tmp, g_woT, b_o, out, nullptr,
              BS * LQ, 256, blockIdx.x * 128, blockIdx.y * 128);
}

// ========= fused transpose+convert of all weights + bias pack ==============
__global__ void transpose_all(const float* __restrict__ w_v,
                              const float* __restrict__ w_off,
                              const float* __restrict__ w_attn,
                              const float* __restrict__ w_o,
                              const float* __restrict__ b_off,
                              const float* __restrict__ b_attn)
{
    const int z = blockIdx.z;
    const int tid = threadIdx.y * 32 + threadIdx.x;
    if (z == 4) {
        if (blockIdx.x == 0 && blockIdx.y == 0) {
            if (tid < 256) g_bq[tid] = b_off[tid];
            if (tid < 128) g_bq[256 + tid] = b_attn[tid];
        }
        return;
    }
    const float* src = (z == 0) ? w_v : (z == 1) ? w_off : (z == 2) ? w_attn : w_o;
    __half* dst      = (z == 0) ? g_wvT : (z == 1) ? g_wqT : (z == 2) ? (g_wqT + 256 * DD) : g_woT;
    const int N = (z == 2) ? 128 : 256;
    if (blockIdx.x * 32 >= N) return;

    __shared__ float t[32][33];
    const int n0 = blockIdx.x * 32;
    const int k0 = blockIdx.y * 32;
    const int x = threadIdx.x, y = threadIdx.y;   // 32 x 8
#pragma unroll
    for (int i = 0; i < 32; i += 8)
        t[y + i][x] = src[(size_t)(k0 + y + i) * N + n0 + x];
    __syncthreads();
#pragma unroll
    for (int i = 0; i < 32; i += 8)
        dst[(size_t)(n0 + y + i) * 256 + k0 + x] = __float2half(t[x][y + i]);
}

// ---------------- fused softmax + bilinear sampling + aggregation ----------
__global__ __launch_bounds__(256)
void sample_agg_kernel(const float* __restrict__ ref)
{
    __shared__ __align__(16) float2 swo[128][4];   // .x weight, .y byte offset

    const int bq  = blockIdx.x;
    const int b   = bq / LQ;
    const int tid = threadIdx.x;

    const int Wl[NL] = {80, 40, 20, 10};
    const int St[NL] = {0, 6400, 8000, 8400};

    if (tid < 128) {
        const int t = tid;
        const int h = t >> 4;
        const int i = t & 15;
        const int l = i >> 2;

        float logit = g_offattn[(size_t)bq * 384 + 256 + t];
        float m = logit;
#pragma unroll
        for (int d = 8; d; d >>= 1) m = fmaxf(m, __shfl_xor_sync(0xffffffffu, m, d, 16));
        float e = __expf(logit - m);
        float s = e;
#pragma unroll
        for (int d = 8; d; d >>= 1) s += __shfl_xor_sync(0xffffffffu, s, d, 16);
        const float aw = e / s;

        const float ox = g_offattn[(size_t)bq * 384 + 2 * t];
        const float oy = g_offattn[(size_t)bq * 384 + 2 * t + 1];
        const float rx = ref[((size_t)bq * NL + l) * 2 + 0];
        const float ry = ref[((size_t)bq * NL + l) * 2 + 1];

        const int   W = Wl[l], H = Wl[l];
        const float Wf = (float)W;

        const float x = fmaf(rx, Wf, ox) - 0.5f;
        const float y = fmaf(ry, Wf, oy) - 0.5f;
        const float x0f = floorf(x), y0f = floorf(y);
        const int   x0 = (int)x0f,  y0 = (int)y0f;
        const float fx = x - x0f,   fy = y - y0f;

        const float w00 = (1.f - fx) * (1.f - fy) * aw;
        const float w10 = fx * (1.f - fy) * aw;
        const float w01 = (1.f - fx) * fy * aw;
        const float w11 = fx * fy * aw;

        const bool vx0 = (x0 >= 0) && (x0 < W);
        const bool vx1 = (x0 + 1 >= 0) && (x0 + 1 < W);
        const bool vy0 = (y0 >= 0) && (y0 < H);
        const bool vy1 = (y0 + 1 >= 0) && (y0 + 1 < H);

        const int pbase = b * LV + St[l];
        const int hoff  = h * CC;

        const int i00 = ((pbase + y0 * W + x0) * DD + hoff) << 1;   // fp16 byte offs
        const int i10 = i00 + (DD << 1);
        const int i01 = i00 + (W * DD << 1);
        const int i11 = i01 + (DD << 1);

        swo[t][0] = make_float2((vx0 && vy0) ? w00 : 0.f, __int_as_float((vx0 && vy0) ? i00 : 0));
        swo[t][1] = make_float2((vx1 && vy0) ? w10 : 0.f, __int_as_float((vx1 && vy0) ? i10 : 0));
        swo[t][2] = make_float2((vx0 && vy1) ? w01 : 0.f, __int_as_float((vx0 && vy1) ? i01 : 0));
        swo[t][3] = make_float2((vx1 && vy1) ? w11 : 0.f, __int_as_float((vx1 && vy1) ? i11 : 0));
    }
    __syncthreads();

    const int h    = tid >> 5;
    const int lane = tid & 31;
    const int lh   = lane >> 4;
    const int ch   = (lane & 15) * 2;
    const char* base = (const char*)g_vph + (ch << 1);

    float accx = 0.f, accy = 0.f;
#pragma unroll
    for (int i = 0; i < 8; i++) {
        const int t = h * 16 + i * 2 + lh;
        float4 p01 = *(const float4*)(&swo[t][0]);
        float4 p23 = *(const float4*)(&swo[t][2]);
#pragma unroll
        for (int c = 0; c < 4; c++) {
            const float w   = (c == 0) ? p01.x : (c == 1) ? p01.z : (c == 2) ? p23.x : p23.z;
            const float off = (c == 0) ? p01.y : (c == 1) ? p01.w : (c == 2) ? p23.y : p23.w;
            const __half2 v = *(const __half2*)(base + __float_as_int(off));
            const float2 f  = __half22float2(v);
            accx = fmaf(w, f.x, accx);
            accy = fmaf(w, f.y, accy);
        }
    }
    accx += __shfl_xor_sync(0xffffffffu, accx, 16);
    accy += __shfl_xor_sync(0xffffffffu, accy, 16);
    if (lh == 0)
        *(float2*)(g_tmp + (size_t)bq * DD + h * CC + ch) = make_float2(accx, accy);
}

// ---------------------------------------------------------------------------
extern "C" void kernel_launch(void* const* d_in, const int* in_sizes, int n_in,
                              void* d_out, int out_size)
{
    const float* query  = (const float*)d_in[0];
    const float* refpts = (const float*)d_in[1];
    const float* value  = (const float*)d_in[2];
    const float* w_off  = (const float*)d_in[3];
    const float* b_off  = (const float*)d_in[4];
    const float* w_attn = (const float*)d_in[5];
    const float* b_attn = (const float*)d_in[6];
    const float* w_v    = (const float*)d_in[7];
    const float* b_v    = (const float*)d_in[8];
    const float* w_o    = (const float*)d_in[9];
    const float* b_o    = (const float*)d_in[10];
    float* out = (float*)d_out;

    cudaFuncSetAttribute(gemm_fused, cudaFuncAttributeMaxDynamicSharedMemorySize, SMEM_GEMM);
    cudaFuncSetAttribute(gemm_k4,    cudaFuncAttributeMaxDynamicSharedMemorySize, SMEM_GEMM);

    // weight transposes + bias pack (one launch)
    transpose_all<<<dim3(8, 8, 5), dim3(32, 8)>>>(w_v, w_off, w_attn, w_o, b_off, b_attn);

    // K1 (value proj -> fp16 Vp) + K2 (query -> off|attn), fused single launch
    gemm_fused<<<K1_BLOCKS + K2_BLOCKS, 256, SMEM_GEMM>>>(value, query, b_v);

    // K3: softmax + sampling + aggregation -> fp32
    sample_agg_kernel<<<BS * LQ, 256>>>(refpts);

    // K4: out = tmp @ w_o + b_o -> fp32
    gemm_k4<<<dim3(K2_TX, 2), 256, SMEM_GEMM>>>(b_o, out);
}

// round 13
// speedup vs baseline: 4.2527x; 1.0006x over previous
#include <cuda_runtime.h>
#include <cuda_fp16.h>
#include <cstdint>
#include <math.h>

#define BS 8
#define LQ 1000
#define DD 256
#define NH 8
#define NL 4
#define NP 4
#define CC 32
#define LV 8500   // 80*80 + 40*40 + 20*20 + 10*10

// ---------------- scratch (static device globals; no dynamic alloc) --------
__device__ __align__(16) __half g_vph [(size_t)BS * LV * DD];   // projected value fp16
__device__ __align__(16) float  g_offattn[(size_t)BS * LQ * 384]; // off(256) | attn(128)
__device__ __align__(16) __half g_tmph[(size_t)BS * LQ * DD];   // aggregated fp16
__device__ __align__(16) __half g_wvT [DD * DD];                // [N][K] fp16
__device__ __align__(16) __half g_wqT [384 * DD];               // [w_off^T ; w_attn^T]
__device__ __align__(16) float  g_bq  [384];                    // b_off | b_attn
__device__ __align__(16) __half g_woT [DD * DD];

// ======================= helpers ===========================================
__device__ __forceinline__ void cpasync16(uint32_t dst, const void* src) {
    asm volatile("cp.async.cg.shared.global [%0], [%1], 16;" :: "r"(dst), "l"(src));
}
__device__ __forceinline__ void cp_commit() { asm volatile("cp.async.commit_group;"); }

__device__ __forceinline__ uint32_t ld2cvt(const float* p) {
    float2 f = *(const float2*)p;
    __half2 h = __floats2half2_rn(f.x, f.y);
    return *(uint32_t*)&h;
}

__device__ __forceinline__ void mma16816(float* a4, uint32_t a0, uint32_t a1,
                                         uint32_t a2, uint32_t a3,
                                         uint32_t b0, uint32_t b1) {
    asm volatile(
        "mma.sync.aligned.m16n8k16.row.col.f32.f16.f16.f32 "
        "{%0,%1,%2,%3}, {%4,%5,%6,%7}, {%8,%9}, {%0,%1,%2,%3};"
        : "+f"(a4[0]), "+f"(a4[1]), "+f"(a4[2]), "+f"(a4[3])
        : "r"(a0), "r"(a1), "r"(a2), "r"(a3), "r"(b0), "r"(b1));
}

// ====== fp32-A tensor-core GEMM body (K=256, tile 128x128, BK=32) ==========
#define LDA 36
#define LDB 40
#define STG_A (128 * LDA)
#define STG_B (128 * LDB)
#define SMEM_A_BYTES (3 * STG_A * 4)                   // 55296
#define SMEM_GEMM    (SMEM_A_BYTES + 3 * STG_B * 2)    // 86016

// fp16-A variant smem: A stage = 128 x LDB halves
#define SMEM_AH_BYTES (3 * STG_B * 2)                  // 30720
#define SMEM_GEMM_H   (2 * SMEM_AH_BYTES)              // 61440

__device__ __forceinline__
void gemm_body(const float* __restrict__ A, const __half* __restrict__ BT,
               const float* __restrict__ bias, float* __restrict__ Cf,
               __half* __restrict__ Ch, int M, int N, int brow, int ncol)
{
    extern __shared__ __align__(16) char smem[];
    float*  As = (float*)smem;
    __half* Bs = (__half*)(smem + SMEM_A_BYTES);

    const int tid  = threadIdx.x;
    const int wid  = tid >> 5;
    const int lane = tid & 31;
    const int wm   = (wid & 3) * 32;
    const int wn   = (wid >> 2) * 64;
    const int grp  = lane >> 2;
    const int tig  = lane & 3;

    float acc[2][8][4];
#pragma unroll
    for (int i = 0; i < 2; i++)
#pragma unroll
        for (int j = 0; j < 8; j++)
#pragma unroll
            for (int r = 0; r < 4; r++) acc[i][j][r] = 0.f;

    auto load = [&](int kb, int stg) {
#pragma unroll
        for (int t = 0; t < 4; t++) {
            const int lin = tid + t * 256;
            const int row = lin >> 3;
            const int c   = lin & 7;
            const float* sa = A + (size_t)min(brow + row, M - 1) * 256 + kb + c * 4;
            cpasync16((uint32_t)__cvta_generic_to_shared(&As[stg * STG_A + row * LDA + c * 4]), sa);
        }
#pragma unroll
        for (int t = 0; t < 2; t++) {
            const int lin = tid + t * 256;
            const int row = lin >> 2;
            const int c   = lin & 3;
            const __half* sb = BT + (size_t)(ncol + row) * 256 + kb + c * 8;
            cpasync16((uint32_t)__cvta_generic_to_shared(&Bs[stg * STG_B + row * LDB + c * 8]), sb);
        }
        cp_commit();
    };

    load(0, 0);
    load(32, 1);

    for (int it = 0; it < 8; it++) {
        const int buf = it % 3;
        if (it + 2 < 8) load((it + 2) * 32, (it + 2) % 3);
        if (it < 6)       asm volatile("cp.async.wait_group 2;");
        else if (it == 6) asm volatile("cp.async.wait_group 1;");
        else              asm volatile("cp.async.wait_group 0;");
        __syncthreads();

        const float*  Ab = As + buf * STG_A;
        const __half* Bb = Bs + buf * STG_B;

#pragma unroll
        for (int ks = 0; ks < 2; ks++) {
            const int kh = ks * 16;
            uint32_t af[2][4];
#pragma unroll
            for (int mi = 0; mi < 2; mi++) {
                const int r0 = wm + mi * 16 + grp;
                af[mi][0] = ld2cvt(Ab + (r0    ) * LDA + kh + tig * 2);
                af[mi][1] = ld2cvt(Ab + (r0 + 8) * LDA + kh + tig * 2);
                af[mi][2] = ld2cvt(Ab + (r0    ) * LDA + kh + tig * 2 + 8);
                af[mi][3] = ld2cvt(Ab + (r0 + 8) * LDA + kh + tig * 2 + 8);
            }
#pragma unroll
            for (int j = 0; j < 8; j++) {
                const int nr = wn + j * 8 + grp;
                uint32_t b0 = *(const uint32_t*)&Bb[nr * LDB + kh + tig * 2];
                uint32_t b1 = *(const uint32_t*)&Bb[nr * LDB + kh + tig * 2 + 8];
#pragma unroll
                for (int mi = 0; mi < 2; mi++)
                    mma16816(acc[mi][j], af[mi][0], af[mi][1], af[mi][2], af[mi][3], b0, b1);
            }
        }
        __syncthreads();
    }

#pragma unroll
    for (int mi = 0; mi < 2; mi++) {
#pragma unroll
        for (int j = 0; j < 8; j++) {
            const int col = ncol + wn + j * 8 + 2 * tig;
            const float bx = bias[col], by = bias[col + 1];
            const int r0 = brow + wm + mi * 16 + grp;
            const int r1 = r0 + 8;
            if (Ch) {
                if (r0 < M)
                    *(__half2*)(Ch + (size_t)r0 * N + col) =
                        __floats2half2_rn(acc[mi][j][0] + bx, acc[mi][j][1] + by);
                if (r1 < M)
                    *(__half2*)(Ch + (size_t)r1 * N + col) =
                        __floats2half2_rn(acc[mi][j][2] + bx, acc[mi][j][3] + by);
            } else {
                if (r0 < M)
                    *(float2*)(Cf + (size_t)r0 * N + col) =
                        make_float2(acc[mi][j][0] + bx, acc[mi][j][1] + by);
                if (r1 < M)
                    *(float2*)(Cf + (size_t)r1 * N + col) =
                        make_float2(acc[mi][j][2] + bx, acc[mi][j][3] + by);
            }
        }
    }
}

// ====== fp16-A GEMM body (A and B both fp16 K-major; K4 path) ==============
__device__ __forceinline__
void gemm_body_h(const __half* __restrict__ A, const __half* __restrict__ BT,
                 const float* __restrict__ bias, float* __restrict__ Cf,
                 int M, int N, int brow, int ncol)
{
    extern __shared__ __align__(16) char smem[];
    __half* As = (__half*)smem;                        // [3][128][LDB]
    __half* Bs = (__half*)(smem + SMEM_AH_BYTES);

    const int tid  = threadIdx.x;
    const int wid  = tid >> 5;
    const int lane = tid & 31;
    const int wm   = (wid & 3) * 32;
    const int wn   = (wid >> 2) * 64;
    const int grp  = lane >> 2;
    const int tig  = lane & 3;

    float acc[2][8][4];
#pragma unroll
    for (int i = 0; i < 2; i++)
#pragma unroll
        for (int j = 0; j < 8; j++)
#pragma unroll
            for (int r = 0; r < 4; r++) acc[i][j][r] = 0.f;

    auto load = [&](int kb, int stg) {
#pragma unroll
        for (int t = 0; t < 2; t++) {
            const int lin = tid + t * 256;
            const int row = lin >> 2;
            const int c   = lin & 3;
            const __half* sa = A + (size_t)min(brow + row, M - 1) * 256 + kb + c * 8;
            cpasync16((uint32_t)__cvta_generic_to_shared(&As[stg * STG_B + row * LDB + c * 8]), sa);
            const __half* sb = BT + (size_t)(ncol + row) * 256 + kb + c * 8;
            cpasync16((uint32_t)__cvta_generic_to_shared(&Bs[stg * STG_B + row * LDB + c * 8]), sb);
        }
        cp_commit();
    };

    load(0, 0);
    load(32, 1);

    for (int it = 0; it < 8; it++) {
        const int buf = it % 3;
        if (it + 2 < 8) load((it + 2) * 32, (it + 2) % 3);
        if (it < 6)       asm volatile("cp.async.wait_group 2;");
        else if (it == 6) asm volatile("cp.async.wait_group 1;");
        else              asm volatile("cp.async.wait_group 0;");
        __syncthreads();

        const __half* Ab = As + buf * STG_B;
        const __half* Bb = Bs + buf * STG_B;

#pragma unroll
        for (int ks = 0; ks < 2; ks++) {
            const int kh = ks * 16;
            uint32_t af[2][4];
#pragma unroll
            for (int mi = 0; mi < 2; mi++) {
                const int r0 = wm + mi * 16 + grp;
                af[mi][0] = *(const uint32_t*)&Ab[(r0    ) * LDB + kh + tig * 2];
                af[mi][1] = *(const uint32_t*)&Ab[(r0 + 8) * LDB + kh + tig * 2];
                af[mi][2] = *(const uint32_t*)&Ab[(r0    ) * LDB + kh + tig * 2 + 8];
                af[mi][3] = *(const uint32_t*)&Ab[(r0 + 8) * LDB + kh + tig * 2 + 8];
            }
#pragma unroll
            for (int j = 0; j < 8; j++) {
                const int nr = wn + j * 8 + grp;
                uint32_t b0 = *(const uint32_t*)&Bb[nr * LDB + kh + tig * 2];
                uint32_t b1 = *(const uint32_t*)&Bb[nr * LDB + kh + tig * 2 + 8];
#pragma unroll
                for (int mi = 0; mi < 2; mi++)
                    mma16816(acc[mi][j], af[mi][0], af[mi][1], af[mi][2], af[mi][3], b0, b1);
            }
        }
        __syncthreads();
    }

#pragma unroll
    for (int mi = 0; mi < 2; mi++) {
#pragma unroll
        for (int j = 0; j < 8; j++) {
            const int col = ncol + wn + j * 8 + 2 * tig;
            const float bx = bias[col], by = bias[col + 1];
            const int r0 = brow + wm + mi * 16 + grp;
            const int r1 = r0 + 8;
            if (r0 < M)
                *(float2*)(Cf + (size_t)r0 * N + col) =
                    make_float2(acc[mi][j][0] + bx, acc[mi][j][1] + by);
            if (r1 < M)
                *(float2*)(Cf + (size_t)r1 * N + col) =
                    make_float2(acc[mi][j][2] + bx, acc[mi][j][3] + by);
        }
    }
}

// ---- fused K1+K2: one launch; K2's latency-bound blocks scheduled first ----
#define K1_TX 532
#define K2_TX 63
#define K2_BLOCKS (K2_TX * 3)
#define K1_BLOCKS (K1_TX * 2)

__global__ __launch_bounds__(256, 2)
void gemm_fused(const float* __restrict__ value, const float* __restrict__ query,
                const float* __restrict__ b_v)
{
    const int bid = blockIdx.x;
    if (bid < K2_BLOCKS) {
        const int bx = bid % K2_TX, by = bid / K2_TX;
        gemm_body(query, g_wqT, g_bq, g_offattn, nullptr,
                  BS * LQ, 384, bx * 128, by * 128);
    } else {
        const int r = bid - K2_BLOCKS;
        const int bx = r % K1_TX, by = r / K1_TX;
        gemm_body(value, g_wvT, b_v, nullptr, g_vph,
                  BS * LV, 256, bx * 128, by * 128);
    }
}

// ---- K4 (fp16 A) ----------------------------------------------------------
__global__ __launch_bounds__(256, 2)
void gemm_k4(const float* __restrict__ b_o, float* __restrict__ out)
{
    gemm_body_h(g_tmph, g_woT, b_o, out,
                BS * LQ, 256, blockIdx.x * 128, blockIdx.y * 128);
}

// ========= fused transpose+convert of all weights + bias pack ==============
__global__ void transpose_all(const float* __restrict__ w_v,
                              const float* __restrict__ w_off,
                              const float* __restrict__ w_attn,
                              const float* __restrict__ w_o,
                              const float* __restrict__ b_off,
                              const float* __restrict__ b_attn)
{
    const int z = blockIdx.z;
    const int tid = threadIdx.y * 32 + threadIdx.x;
    if (z == 4) {
        if (blockIdx.x == 0 && blockIdx.y == 0) {
            if (tid < 256) g_bq[tid] = b_off[tid];
            if (tid < 128) g_bq[256 + tid] = b_attn[tid];
        }
        return;
    }
    const float* src = (z == 0) ? w_v : (z == 1) ? w_off : (z == 2) ? w_attn : w_o;
    __half* dst      = (z == 0) ? g_wvT : (z == 1) ? g_wqT : (z == 2) ? (g_wqT + 256 * DD) : g_woT;
    const int N = (z == 2) ? 128 : 256;
    if (blockIdx.x * 32 >= N) return;

    __shared__ float t[32][33];
    const int n0 = blockIdx.x * 32;
    const int k0 = blockIdx.y * 32;
    const int x = threadIdx.x, y = threadIdx.y;   // 32 x 8
#pragma unroll
    for (int i = 0; i < 32; i += 8)
        t[y + i][x] = src[(size_t)(k0 + y + i) * N + n0 + x];
    __syncthreads();
#pragma unroll
    for (int i = 0; i < 32; i += 8)
        dst[(size_t)(n0 + y + i) * 256 + k0 + x] = __float2half(t[x][y + i]);
}

// ---------------- fused softmax + bilinear sampling + aggregation ----------
__global__ __launch_bounds__(256)
void sample_agg_kernel(const float* __restrict__ ref)
{
    __shared__ __align__(16) float2 swo[128][4];   // .x weight, .y byte offset

    const int bq  = blockIdx.x;
    const int b   = bq / LQ;
    const int tid = threadIdx.x;

    const int Wl[NL] = {80, 40, 20, 10};
    const int St[NL] = {0, 6400, 8000, 8400};

    if (tid < 128) {
        const int t = tid;
        const int h = t >> 4;
        const int i = t & 15;
        const int l = i >> 2;

        float logit = g_offattn[(size_t)bq * 384 + 256 + t];
        float m = logit;
#pragma unroll
        for (int d = 8; d; d >>= 1) m = fmaxf(m, __shfl_xor_sync(0xffffffffu, m, d, 16));
        float e = __expf(logit - m);
        float s = e;
#pragma unroll
        for (int d = 8; d; d >>= 1) s += __shfl_xor_sync(0xffffffffu, s, d, 16);
        const float aw = e / s;

        const float ox = g_offattn[(size_t)bq * 384 + 2 * t];
        const float oy = g_offattn[(size_t)bq * 384 + 2 * t + 1];
        const float rx = ref[((size_t)bq * NL + l) * 2 + 0];
        const float ry = ref[((size_t)bq * NL + l) * 2 + 1];

        const int   W = Wl[l], H = Wl[l];
        const float Wf = (float)W;

        const float x = fmaf(rx, Wf, ox) - 0.5f;
        const float y = fmaf(ry, Wf, oy) - 0.5f;
        const float x0f = floorf(x), y0f = floorf(y);
        const int   x0 = (int)x0f,  y0 = (int)y0f;
        const float fx = x - x0f,   fy = y - y0f;

        const float w00 = (1.f - fx) * (1.f - fy) * aw;
        const float w10 = fx * (1.f - fy) * aw;
        const float w01 = (1.f - fx) * fy * aw;
        const float w11 = fx * fy * aw;

        const bool vx0 = (x0 >= 0) && (x0 < W);
        const bool vx1 = (x0 + 1 >= 0) && (x0 + 1 < W);
        const bool vy0 = (y0 >= 0) && (y0 < H);
        const bool vy1 = (y0 + 1 >= 0) && (y0 + 1 < H);

        const int pbase = b * LV + St[l];
        const int hoff  = h * CC;

        const int i00 = ((pbase + y0 * W + x0) * DD + hoff) << 1;   // fp16 byte offs
        const int i10 = i00 + (DD << 1);
        const int i01 = i00 + (W * DD << 1);
        const int i11 = i01 + (DD << 1);

        swo[t][0] = make_float2((vx0 && vy0) ? w00 : 0.f, __int_as_float((vx0 && vy0) ? i00 : 0));
        swo[t][1] = make_float2((vx1 && vy0) ? w10 : 0.f, __int_as_float((vx1 && vy0) ? i10 : 0));
        swo[t][2] = make_float2((vx0 && vy1) ? w01 : 0.f, __int_as_float((vx0 && vy1) ? i01 : 0));
        swo[t][3] = make_float2((vx1 && vy1) ? w11 : 0.f, __int_as_float((vx1 && vy1) ? i11 : 0));
    }
    __syncthreads();

    const int h    = tid >> 5;
    const int lane = tid & 31;
    const int lh   = lane >> 4;
    const int ch   = (lane & 15) * 2;
    const char* base = (const char*)g_vph + (ch << 1);

    float accx = 0.f, accy = 0.f;
#pragma unroll
    for (int i = 0; i < 8; i++) {
        const int t = h * 16 + i * 2 + lh;
        float4 p01 = *(const float4*)(&swo[t][0]);
        float4 p23 = *(const float4*)(&swo[t][2]);
#pragma unroll
        for (int c = 0; c < 4; c++) {
            const float w   = (c == 0) ? p01.x : (c == 1) ? p01.z : (c == 2) ? p23.x : p23.z;
            const float off = (c == 0) ? p01.y : (c == 1) ? p01.w : (c == 2) ? p23.y : p23.w;
            const __half2 v = *(const __half2*)(base + __float_as_int(off));
            const float2 f  = __half22float2(v);
            accx = fmaf(w, f.x, accx);
            accy = fmaf(w, f.y, accy);
        }
    }
    accx += __shfl_xor_sync(0xffffffffu, accx, 16);
    accy += __shfl_xor_sync(0xffffffffu, accy, 16);
    if (lh == 0)
        *(__half2*)(g_tmph + (size_t)bq * DD + h * CC + ch) = __floats2half2_rn(accx, accy);
}

// ---------------------------------------------------------------------------
extern "C" void kernel_launch(void* const* d_in, const int* in_sizes, int n_in,
                              void* d_out, int out_size)
{
    const float* query  = (const float*)d_in[0];
    const float* refpts = (const float*)d_in[1];
    const float* value  = (const float*)d_in[2];
    const float* w_off  = (const float*)d_in[3];
    const float* b_off  = (const float*)d_in[4];
    const float* w_attn = (const float*)d_in[5];
    const float* b_attn = (const float*)d_in[6];
    const float* w_v    = (const float*)d_in[7];
    const float* b_v    = (const float*)d_in[8];
    const float* w_o    = (const float*)d_in[9];
    const float* b_o    = (const float*)d_in[10];
    float* out = (float*)d_out;

    cudaFuncSetAttribute(gemm_fused, cudaFuncAttributeMaxDynamicSharedMemorySize, SMEM_GEMM);
    cudaFuncSetAttribute(gemm_k4,    cudaFuncAttributeMaxDynamicSharedMemorySize, SMEM_GEMM_H);

    // weight transposes + bias pack (one launch)
    transpose_all<<<dim3(8, 8, 5), dim3(32, 8)>>>(w_v, w_off, w_attn, w_o, b_off, b_attn);

    // K1 (value proj -> fp16 Vp) + K2 (query -> off|attn), fused single launch
    gemm_fused<<<K1_BLOCKS + K2_BLOCKS, 256, SMEM_GEMM>>>(value, query, b_v);

    // K3: softmax + sampling + aggregation -> fp16
    sample_agg_kernel<<<BS * LQ, 256>>>(refpts);

    // K4: out = tmph @ w_o + b_o -> fp32 (fp16-A path)
    gemm_k4<<<dim3(K2_TX, 2), 256, SMEM_GEMM_H>>>(b_o, out);
}

// round 14
// speedup vs baseline: 4.4863x; 1.0549x over previous
#include <cuda_runtime.h>
#include <cuda_fp16.h>
#include <cstdint>
#include <math.h>

#define BS 8
#define LQ 1000
#define DD 256
#define NH 8
#define NL 4
#define NP 4
#define CC 32
#define LV 8500   // 80*80 + 40*40 + 20*20 + 10*10

// ---------------- scratch (static device globals; no dynamic alloc) --------
__device__ __align__(16) __half g_vph [(size_t)BS * LV * DD];   // projected value fp16
__device__ __align__(16) float  g_offattn[(size_t)BS * LQ * 384]; // off(256) | attn(128)
__device__ __align__(16) __half g_tmph[(size_t)BS * LQ * DD];   // aggregated fp16
__device__ __align__(16) __half g_wvT [DD * DD];                // [N][K] fp16
__device__ __align__(16) __half g_wqT [384 * DD];               // [w_off^T ; w_attn^T]
__device__ __align__(16) float  g_bq  [384];                    // b_off | b_attn
__device__ __align__(16) __half g_woT [DD * DD];

// ======================= helpers ===========================================
__device__ __forceinline__ void cpasync16(uint32_t dst, const void* src) {
    asm volatile("cp.async.cg.shared.global [%0], [%1], 16;" :: "r"(dst), "l"(src));
}
__device__ __forceinline__ void cp_commit() { asm volatile("cp.async.commit_group;"); }

__device__ __forceinline__ uint32_t ld2cvt(const float* p) {
    float2 f = *(const float2*)p;
    __half2 h = __floats2half2_rn(f.x, f.y);
    return *(uint32_t*)&h;
}

__device__ __forceinline__ void mma16816(float* a4, uint32_t a0, uint32_t a1,
                                         uint32_t a2, uint32_t a3,
                                         uint32_t b0, uint32_t b1) {
    asm volatile(
        "mma.sync.aligned.m16n8k16.row.col.f32.f16.f16.f32 "
        "{%0,%1,%2,%3}, {%4,%5,%6,%7}, {%8,%9}, {%0,%1,%2,%3};"
        : "+f"(a4[0]), "+f"(a4[1]), "+f"(a4[2]), "+f"(a4[3])
        : "r"(a0), "r"(a1), "r"(a2), "r"(a3), "r"(b0), "r"(b1));
}

// ====== fp32-A tensor-core GEMM body (K=256, tile 128x128, BK=32) ==========
#define LDA 36
#define LDB 40
#define STG_A (128 * LDA)
#define STG_B (128 * LDB)
#define SMEM_A_BYTES (3 * STG_A * 4)                   // 55296
#define SMEM_GEMM    (SMEM_A_BYTES + 3 * STG_B * 2)    // 86016

#define SMEM_AH_BYTES (3 * STG_B * 2)                  // 30720
#define SMEM_GEMM_H   (2 * SMEM_AH_BYTES)              // 61440

__device__ __forceinline__
void gemm_body(const float* __restrict__ A, const __half* __restrict__ BT,
               const float* __restrict__ bias, float* __restrict__ Cf,
               __half* __restrict__ Ch, int M, int N, int brow, int ncol)
{
    extern __shared__ __align__(16) char smem[];
    float*  As = (float*)smem;
    __half* Bs = (__half*)(smem + SMEM_A_BYTES);

    const int tid  = threadIdx.x;
    const int wid  = tid >> 5;
    const int lane = tid & 31;
    const int wm   = (wid & 3) * 32;
    const int wn   = (wid >> 2) * 64;
    const int grp  = lane >> 2;
    const int tig  = lane & 3;

    float acc[2][8][4];
#pragma unroll
    for (int i = 0; i < 2; i++)
#pragma unroll
        for (int j = 0; j < 8; j++)
#pragma unroll
            for (int r = 0; r < 4; r++) acc[i][j][r] = 0.f;

    auto load = [&](int kb, int stg) {
#pragma unroll
        for (int t = 0; t < 4; t++) {
            const int lin = tid + t * 256;
            const int row = lin >> 3;
            const int c   = lin & 7;
            const float* sa = A + (size_t)min(brow + row, M - 1) * 256 + kb + c * 4;
            cpasync16((uint32_t)__cvta_generic_to_shared(&As[stg * STG_A + row * LDA + c * 4]), sa);
        }
#pragma unroll
        for (int t = 0; t < 2; t++) {
            const int lin = tid + t * 256;
            const int row = lin >> 2;
            const int c   = lin & 3;
            const __half* sb = BT + (size_t)(ncol + row) * 256 + kb + c * 8;
            cpasync16((uint32_t)__cvta_generic_to_shared(&Bs[stg * STG_B + row * LDB + c * 8]), sb);
        }
        cp_commit();
    };

    load(0, 0);
    load(32, 1);

    for (int it = 0; it < 8; it++) {
        const int buf = it % 3;
        if (it + 2 < 8) load((it + 2) * 32, (it + 2) % 3);
        if (it < 6)       asm volatile("cp.async.wait_group 2;");
        else if (it == 6) asm volatile("cp.async.wait_group 1;");
        else              asm volatile("cp.async.wait_group 0;");
        __syncthreads();

        const float*  Ab = As + buf * STG_A;
        const __half* Bb = Bs + buf * STG_B;

#pragma unroll
        for (int ks = 0; ks < 2; ks++) {
            const int kh = ks * 16;
            uint32_t af[2][4];
#pragma unroll
            for (int mi = 0; mi < 2; mi++) {
                const int r0 = wm + mi * 16 + grp;
                af[mi][0] = ld2cvt(Ab + (r0    ) * LDA + kh + tig * 2);
                af[mi][1] = ld2cvt(Ab + (r0 + 8) * LDA + kh + tig * 2);
                af[mi][2] = ld2cvt(Ab + (r0    ) * LDA + kh + tig * 2 + 8);
                af[mi][3] = ld2cvt(Ab + (r0 + 8) * LDA + kh + tig * 2 + 8);
            }
#pragma unroll
            for (int j = 0; j < 8; j++) {
                const int nr = wn + j * 8 + grp;
                uint32_t b0 = *(const uint32_t*)&Bb[nr * LDB + kh + tig * 2];
                uint32_t b1 = *(const uint32_t*)&Bb[nr * LDB + kh + tig * 2 + 8];
#pragma unroll
                for (int mi = 0; mi < 2; mi++)
                    mma16816(acc[mi][j], af[mi][0], af[mi][1], af[mi][2], af[mi][3], b0, b1);
            }
        }
        __syncthreads();
    }

#pragma unroll
    for (int mi = 0; mi < 2; mi++) {
#pragma unroll
        for (int j = 0; j < 8; j++) {
            const int col = ncol + wn + j * 8 + 2 * tig;
            const float bx = bias[col], by = bias[col + 1];
            const int r0 = brow + wm + mi * 16 + grp;
            const int r1 = r0 + 8;
            if (Ch) {
                if (r0 < M)
                    *(__half2*)(Ch + (size_t)r0 * N + col) =
                        __floats2half2_rn(acc[mi][j][0] + bx, acc[mi][j][1] + by);
                if (r1 < M)
                    *(__half2*)(Ch + (size_t)r1 * N + col) =
                        __floats2half2_rn(acc[mi][j][2] + bx, acc[mi][j][3] + by);
            } else {
                if (r0 < M)
                    *(float2*)(Cf + (size_t)r0 * N + col) =
                        make_float2(acc[mi][j][0] + bx, acc[mi][j][1] + by);
                if (r1 < M)
                    *(float2*)(Cf + (size_t)r1 * N + col) =
                        make_float2(acc[mi][j][2] + bx, acc[mi][j][3] + by);
            }
        }
    }
}

// ====== fp16-A GEMM body (A and B both fp16 K-major; K4 path) ==============
__device__ __forceinline__
void gemm_body_h(const __half* __restrict__ A, const __half* __restrict__ BT,
                 const float* __restrict__ bias, float* __restrict__ Cf,
                 int M, int N, int brow, int ncol)
{
    extern __shared__ __align__(16) char smem[];
    __half* As = (__half*)smem;                        // [3][128][LDB]
    __half* Bs = (__half*)(smem + SMEM_AH_BYTES);

    const int tid  = threadIdx.x;
    const int wid  = tid >> 5;
    const int lane = tid & 31;
    const int wm   = (wid & 3) * 32;
    const int wn   = (wid >> 2) * 64;
    const int grp  = lane >> 2;
    const int tig  = lane & 3;

    float acc[2][8][4];
#pragma unroll
    for (int i = 0; i < 2; i++)
#pragma unroll
        for (int j = 0; j < 8; j++)
#pragma unroll
            for (int r = 0; r < 4; r++) acc[i][j][r] = 0.f;

    auto load = [&](int kb, int stg) {
#pragma unroll
        for (int t = 0; t < 2; t++) {
            const int lin = tid + t * 256;
            const int row = lin >> 2;
            const int c   = lin & 3;
            const __half* sa = A + (size_t)min(brow + row, M - 1) * 256 + kb + c * 8;
            cpasync16((uint32_t)__cvta_generic_to_shared(&As[stg * STG_B + row * LDB + c * 8]), sa);
            const __half* sb = BT + (size_t)(ncol + row) * 256 + kb + c * 8;
            cpasync16((uint32_t)__cvta_generic_to_shared(&Bs[stg * STG_B + row * LDB + c * 8]), sb);
        }
        cp_commit();
    };

    load(0, 0);
    load(32, 1);

    for (int it = 0; it < 8; it++) {
        const int buf = it % 3;
        if (it + 2 < 8) load((it + 2) * 32, (it + 2) % 3);
        if (it < 6)       asm volatile("cp.async.wait_group 2;");
        else if (it == 6) asm volatile("cp.async.wait_group 1;");
        else              asm volatile("cp.async.wait_group 0;");
        __syncthreads();

        const __half* Ab = As + buf * STG_B;
        const __half* Bb = Bs + buf * STG_B;

#pragma unroll
        for (int ks = 0; ks < 2; ks++) {
            const int kh = ks * 16;
            uint32_t af[2][4];
#pragma unroll
            for (int mi = 0; mi < 2; mi++) {
                const int r0 = wm + mi * 16 + grp;
                af[mi][0] = *(const uint32_t*)&Ab[(r0    ) * LDB + kh + tig * 2];
                af[mi][1] = *(const uint32_t*)&Ab[(r0 + 8) * LDB + kh + tig * 2];
                af[mi][2] = *(const uint32_t*)&Ab[(r0    ) * LDB + kh + tig * 2 + 8];
                af[mi][3] = *(const uint32_t*)&Ab[(r0 + 8) * LDB + kh + tig * 2 + 8];
            }
#pragma unroll
            for (int j = 0; j < 8; j++) {
                const int nr = wn + j * 8 + grp;
                uint32_t b0 = *(const uint32_t*)&Bb[nr * LDB + kh + tig * 2];
                uint32_t b1 = *(const uint32_t*)&Bb[nr * LDB + kh + tig * 2 + 8];
#pragma unroll
                for (int mi = 0; mi < 2; mi++)
                    mma16816(acc[mi][j], af[mi][0], af[mi][1], af[mi][2], af[mi][3], b0, b1);
            }
        }
        __syncthreads();
    }

#pragma unroll
    for (int mi = 0; mi < 2; mi++) {
#pragma unroll
        for (int j = 0; j < 8; j++) {
            const int col = ncol + wn + j * 8 + 2 * tig;
            const float bx = bias[col], by = bias[col + 1];
            const int r0 = brow + wm + mi * 16 + grp;
            const int r1 = r0 + 8;
            if (r0 < M)
                *(float2*)(Cf + (size_t)r0 * N + col) =
                    make_float2(acc[mi][j][0] + bx, acc[mi][j][1] + by);
            if (r1 < M)
                *(float2*)(Cf + (size_t)r1 * N + col) =
                    make_float2(acc[mi][j][2] + bx, acc[mi][j][3] + by);
        }
    }
}

// ---- fused K1+K2: one launch; K2's latency-bound blocks scheduled first ----
#define K1_TX 532
#define K2_TX 63
#define K2_BLOCKS (K2_TX * 3)
#define K1_BLOCKS (K1_TX * 2)

__global__ __launch_bounds__(256, 2)
void gemm_fused(const float* __restrict__ value, const float* __restrict__ query,
                const float* __restrict__ b_v)
{
    const int bid = blockIdx.x;
    if (bid < K2_BLOCKS) {
        const int bx = bid % K2_TX, by = bid / K2_TX;
        gemm_body(query, g_wqT, g_bq, g_offattn, nullptr,
                  BS * LQ, 384, bx * 128, by * 128);
    } else {
        const int r = bid - K2_BLOCKS;
        const int bx = r % K1_TX, by = r / K1_TX;
        gemm_body(value, g_wvT, b_v, nullptr, g_vph,
                  BS * LV, 256, bx * 128, by * 128);
    }
}

// ---- K4 (fp16 A) ----------------------------------------------------------
__global__ __launch_bounds__(256, 2)
void gemm_k4(const float* __restrict__ b_o, float* __restrict__ out)
{
    gemm_body_h(g_tmph, g_woT, b_o, out,
                BS * LQ, 256, blockIdx.x * 128, blockIdx.y * 128);
}

// ========= fused transpose+convert of all weights + bias pack ==============
__global__ void transpose_all(const float* __restrict__ w_v,
                              const float* __restrict__ w_off,
                              const float* __restrict__ w_attn,
                              const float* __restrict__ w_o,
                              const float* __restrict__ b_off,
                              const float* __restrict__ b_attn)
{
    const int z = blockIdx.z;
    const int tid = threadIdx.y * 32 + threadIdx.x;
    if (z == 4) {
        if (blockIdx.x == 0 && blockIdx.y == 0) {
            if (tid < 256) g_bq[tid] = b_off[tid];
            if (tid < 128) g_bq[256 + tid] = b_attn[tid];
        }
        return;
    }
    const float* src = (z == 0) ? w_v : (z == 1) ? w_off : (z == 2) ? w_attn : w_o;
    __half* dst      = (z == 0) ? g_wvT : (z == 1) ? g_wqT : (z == 2) ? (g_wqT + 256 * DD) : g_woT;
    const int N = (z == 2) ? 128 : 256;
    if (blockIdx.x * 32 >= N) return;

    __shared__ float t[32][33];
    const int n0 = blockIdx.x * 32;
    const int k0 = blockIdx.y * 32;
    const int x = threadIdx.x, y = threadIdx.y;   // 32 x 8
#pragma unroll
    for (int i = 0; i < 32; i += 8)
        t[y + i][x] = src[(size_t)(k0 + y + i) * N + n0 + x];
    __syncthreads();
#pragma unroll
    for (int i = 0; i < 32; i += 8)
        dst[(size_t)(n0 + y + i) * 256 + k0 + x] = __float2half(t[x][y + i]);
}

// ---------------- fused softmax + bilinear sampling + aggregation ----------
// TWO queries per block. Phase 1: 256 threads = 2 x 128 points (all busy).
// Phase 2: 8 warps (heads); each warp processes BOTH queries interleaved
// (8 independent gathers in flight per iteration); half-warps split the 16
// points, combined via shfl_xor(16).
__global__ __launch_bounds__(256)
void sample_agg_kernel(const float* __restrict__ ref)
{
    __shared__ __align__(16) float2 swo[2][128][4];   // [q][point][corner]

    const int bq0 = blockIdx.x * 2;
    const int tid = threadIdx.x;

    const int Wl[NL] = {80, 40, 20, 10};
    const int St[NL] = {0, 6400, 8000, 8400};

    // ---- phase 1: all 256 threads, one (q, point) each ----
    {
        const int q  = tid >> 7;
        const int t  = tid & 127;
        const int bq = bq0 + q;
        const int b  = bq / LQ;
        const int h  = t >> 4;
        const int i  = t & 15;
        const int l  = i >> 2;

        float logit = g_offattn[(size_t)bq * 384 + 256 + t];
        float m = logit;
#pragma unroll
        for (int d = 8; d; d >>= 1) m = fmaxf(m, __shfl_xor_sync(0xffffffffu, m, d, 16));
        float e = __expf(logit - m);
        float s = e;
#pragma unroll
        for (int d = 8; d; d >>= 1) s += __shfl_xor_sync(0xffffffffu, s, d, 16);
        const float aw = e / s;

        const float ox = g_offattn[(size_t)bq * 384 + 2 * t];
        const float oy = g_offattn[(size_t)bq * 384 + 2 * t + 1];
        const float rx = ref[((size_t)bq * NL + l) * 2 + 0];
        const float ry = ref[((size_t)bq * NL + l) * 2 + 1];

        const int   W = Wl[l], H = Wl[l];
        const float Wf = (float)W;

        const float x = fmaf(rx, Wf, ox) - 0.5f;
        const float y = fmaf(ry, Wf, oy) - 0.5f;
        const float x0f = floorf(x), y0f = floorf(y);
        const int   x0 = (int)x0f,  y0 = (int)y0f;
        const float fx = x - x0f,   fy = y - y0f;

        const float w00 = (1.f - fx) * (1.f - fy) * aw;
        const float w10 = fx * (1.f - fy) * aw;
        const float w01 = (1.f - fx) * fy * aw;
        const float w11 = fx * fy * aw;

        const bool vx0 = (x0 >= 0) && (x0 < W);
        const bool vx1 = (x0 + 1 >= 0) && (x0 + 1 < W);
        const bool vy0 = (y0 >= 0) && (y0 < H);
        const bool vy1 = (y0 + 1 >= 0) && (y0 + 1 < H);

        const int pbase = b * LV + St[l];
        const int hoff  = h * CC;

        const int i00 = ((pbase + y0 * W + x0) * DD + hoff) << 1;   // fp16 byte offs
        const int i10 = i00 + (DD << 1);
        const int i01 = i00 + (W * DD << 1);
        const int i11 = i01 + (DD << 1);

        swo[q][t][0] = make_float2((vx0 && vy0) ? w00 : 0.f, __int_as_float((vx0 && vy0) ? i00 : 0));
        swo[q][t][1] = make_float2((vx1 && vy0) ? w10 : 0.f, __int_as_float((vx1 && vy0) ? i10 : 0));
        swo[q][t][2] = make_float2((vx0 && vy1) ? w01 : 0.f, __int_as_float((vx0 && vy1) ? i01 : 0));
        swo[q][t][3] = make_float2((vx1 && vy1) ? w11 : 0.f, __int_as_float((vx1 && vy1) ? i11 : 0));
    }
    __syncthreads();

    // ---- phase 2: 8 warps = 8 heads; both queries interleaved ----
    const int h    = tid >> 5;
    const int lane = tid & 31;
    const int lh   = lane >> 4;
    const int ch   = (lane & 15) * 2;
    const char* base = (const char*)g_vph + (ch << 1);

    float ax0 = 0.f, ay0 = 0.f, ax1 = 0.f, ay1 = 0.f;
#pragma unroll
    for (int i = 0; i < 8; i++) {
        const int t = h * 16 + i * 2 + lh;
        float4 q0a = *(const float4*)(&swo[0][t][0]);
        float4 q0b = *(const float4*)(&swo[0][t][2]);
        float4 q1a = *(const float4*)(&swo[1][t][0]);
        float4 q1b = *(const float4*)(&swo[1][t][2]);
#pragma unroll
        for (int c = 0; c < 4; c++) {
            const float w0 = (c == 0) ? q0a.x : (c == 1) ? q0a.z : (c == 2) ? q0b.x : q0b.z;
            const float o0 = (c == 0) ? q0a.y : (c == 1) ? q0a.w : (c == 2) ? q0b.y : q0b.w;
            const float w1 = (c == 0) ? q1a.x : (c == 1) ? q1a.z : (c == 2) ? q1b.x : q1b.z;
            const float o1 = (c == 0) ? q1a.y : (c == 1) ? q1a.w : (c == 2) ? q1b.y : q1b.w;
            const __half2 v0 = *(const __half2*)(base + __float_as_int(o0));
            const __half2 v1 = *(const __half2*)(base + __float_as_int(o1));
            const float2 f0 = __half22float2(v0);
            const float2 f1 = __half22float2(v1);
            ax0 = fmaf(w0, f0.x, ax0);
            ay0 = fmaf(w0, f0.y, ay0);
            ax1 = fmaf(w1, f1.x, ax1);
            ay1 = fmaf(w1, f1.y, ay1);
        }
    }
    ax0 += __shfl_xor_sync(0xffffffffu, ax0, 16);
    ay0 += __shfl_xor_sync(0xffffffffu, ay0, 16);
    ax1 += __shfl_xor_sync(0xffffffffu, ax1, 16);
    ay1 += __shfl_xor_sync(0xffffffffu, ay1, 16);
    if (lh == 0) {
        *(__half2*)(g_tmph + (size_t)(bq0    ) * DD + h * CC + ch) = __floats2half2_rn(ax0, ay0);
        *(__half2*)(g_tmph + (size_t)(bq0 + 1) * DD + h * CC + ch) = __floats2half2_rn(ax1, ay1);
    }
}

// ---------------------------------------------------------------------------
extern "C" void kernel_launch(void* const* d_in, const int* in_sizes, int n_in,
                              void* d_out, int out_size)
{
    const float* query  = (const float*)d_in[0];
    const float* refpts = (const float*)d_in[1];
    const float* value  = (const float*)d_in[2];
    const float* w_off  = (const float*)d_in[3];
    const float* b_off  = (const float*)d_in[4];
    const float* w_attn = (const float*)d_in[5];
    const float* b_attn = (const float*)d_in[6];
    const float* w_v    = (const float*)d_in[7];
    const float* b_v    = (const float*)d_in[8];
    const float* w_o    = (const float*)d_in[9];
    const float* b_o    = (const float*)d_in[10];
    float* out = (float*)d_out;

    cudaFuncSetAttribute(gemm_fused, cudaFuncAttributeMaxDynamicSharedMemorySize, SMEM_GEMM);
    cudaFuncSetAttribute(gemm_k4,    cudaFuncAttributeMaxDynamicSharedMemorySize, SMEM_GEMM_H);

    // weight transposes + bias pack (one launch)
    transpose_all<<<dim3(8, 8, 5), dim3(32, 8)>>>(w_v, w_off, w_attn, w_o, b_off, b_attn);

    // K1 (value proj -> fp16 Vp) + K2 (query -> off|attn), fused single launch
    gemm_fused<<<K1_BLOCKS + K2_BLOCKS, 256, SMEM_GEMM>>>(value, query, b_v);

    // K3: softmax + sampling + aggregation -> fp16 (2 queries / block)
    sample_agg_kernel<<<BS * LQ / 2, 256>>>(refpts);

    // K4: out = tmph @ w_o + b_o -> fp32 (fp16-A path)
    gemm_k4<<<dim3(K2_TX, 2), 256, SMEM_GEMM_H>>>(b_o, out);
}